// round 6
// baseline (speedup 1.0000x reference)
#include <cuda_runtime.h>
#include <cuda_bf16.h>
#include <cstdint>

#define N_NODES 100000
#define N_EDGES 1600000
#define N_GRAPHS 64
#define D 128

#define SCAN_T 1024
#define NB ((N_NODES + SCAN_T - 1) / SCAN_T)   // 98

// ---------------- scratch (device globals; no allocation allowed) ----------
__device__ float g_t1[(size_t)N_NODES * D];   // X@W1
__device__ float g_t2[(size_t)N_NODES * D];   // h1@W2
__device__ int   g_deg[N_NODES];              // zeroed by k_fused_ap for next call
__device__ float g_dinv[N_NODES];
__device__ int   g_off[N_NODES + 1];
__device__ int   g_cur[N_NODES];
__device__ uint2 g_csr[N_EDGES];              // .x = src, .y = weight bits
__device__ int   g_bsum[NB];
__device__ float g_pool[N_GRAPHS * D];        // zeroed by k_gemm
__device__ int   g_cnt[N_GRAPHS];
__device__ int   g_is64;
__device__ uint32_t g_Wh[2][D * 64];          // W^T bf16-hi, packed pairs [n][k/2]
__device__ uint32_t g_Wl[2][D * 64];          // W^T bf16-lo

// ---------------- helpers ---------------------------------------------------
__device__ __forceinline__ int load_idx(const void* p, long long i) {
    if (g_is64) return (int)((const long long*)p)[i];
    return ((const int*)p)[i];
}

__device__ __forceinline__ int detect64(const void* ep) {
    const int* p = (const int*)ep;
    int is64 = 1;
    #pragma unroll
    for (int j = 0; j < 8; j++)
        if (p[2 * j + 1] != 0) is64 = 0;
    return is64;
}

// split two fp32 into packed bf16x2 hi + bf16x2 lo (Markidis)
__device__ __forceinline__ void bfsplit2(float a, float b,
                                         uint32_t& h, uint32_t& l) {
    __nv_bfloat162 hv = __float22bfloat162_rn(make_float2(a, b));
    float2 hf = __bfloat1622float2(hv);
    __nv_bfloat162 lv = __float22bfloat162_rn(make_float2(a - hf.x, b - hf.y));
    h = *reinterpret_cast<uint32_t*>(&hv);
    l = *reinterpret_cast<uint32_t*>(&lv);
}

__device__ __forceinline__ void mma16(float* c, const uint32_t* a,
                                      const uint32_t* b) {
    asm volatile(
        "mma.sync.aligned.m16n8k16.row.col.f32.bf16.bf16.f32 "
        "{%0,%1,%2,%3}, {%4,%5,%6,%7}, {%8,%9}, {%0,%1,%2,%3};"
        : "+f"(c[0]), "+f"(c[1]), "+f"(c[2]), "+f"(c[3])
        : "r"(a[0]), "r"(a[1]), "r"(a[2]), "r"(a[3]), "r"(b[0]), "r"(b[1]));
}

// gather one node row: relu( dinv^2*h[node] + sum_e w*h[src] + bias )
// 4 independent accumulator chains for MLP>=4 at low occupancy.
__device__ __forceinline__ float4 gather_row(const float4* __restrict__ h4,
                                             int node, int lane,
                                             const float4 b) {
    float dii = g_dinv[node];
    float sw = dii * dii;
    float4 s0 = h4[(size_t)node * 32 + lane];
    float4 acc[4];
    acc[0] = make_float4(s0.x * sw, s0.y * sw, s0.z * sw, s0.w * sw);
    acc[1] = make_float4(0.f, 0.f, 0.f, 0.f);
    acc[2] = acc[1];
    acc[3] = acc[1];

    int e = g_off[node];
    const int end = g_off[node + 1];
    for (; e + 3 < end; e += 4) {
        uint2 p[4];
        #pragma unroll
        for (int j = 0; j < 4; j++) p[j] = g_csr[e + j];
        float4 v[4];
        #pragma unroll
        for (int j = 0; j < 4; j++) v[j] = h4[(size_t)p[j].x * 32 + lane];
        #pragma unroll
        for (int j = 0; j < 4; j++) {
            float w = __uint_as_float(p[j].y);
            acc[j].x = fmaf(v[j].x, w, acc[j].x);
            acc[j].y = fmaf(v[j].y, w, acc[j].y);
            acc[j].z = fmaf(v[j].z, w, acc[j].z);
            acc[j].w = fmaf(v[j].w, w, acc[j].w);
        }
    }
    for (; e < end; e++) {
        uint2 p = g_csr[e];
        float w = __uint_as_float(p.y);
        float4 v = h4[(size_t)p.x * 32 + lane];
        acc[0].x = fmaf(v.x, w, acc[0].x);
        acc[0].y = fmaf(v.y, w, acc[0].y);
        acc[0].z = fmaf(v.z, w, acc[0].z);
        acc[0].w = fmaf(v.w, w, acc[0].w);
    }
    float4 r;
    r.x = fmaxf(acc[0].x + acc[1].x + acc[2].x + acc[3].x + b.x, 0.f);
    r.y = fmaxf(acc[0].y + acc[1].y + acc[2].y + acc[3].y + b.y, 0.f);
    r.z = fmaxf(acc[0].z + acc[1].z + acc[2].z + acc[3].z + b.z, 0.f);
    r.w = fmaxf(acc[0].w + acc[1].w + acc[2].w + acc[3].w + b.w, 0.f);
    return r;
}

// ---------------- deg count + init (W split/transpose, dtype, off[N]) -------
__global__ void k_deg(const void* ep, const float* W1, const float* W2) {
    int i = blockIdx.x * blockDim.x + threadIdx.x;
    if (i == 0) {
        g_is64 = detect64(ep);
        g_off[N_NODES] = N_EDGES;
    }
    if (i < 2 * D * 64) {          // one u32-pair of W^T per thread
        int m = i >> 13;           // 0 -> W1, 1 -> W2
        int j = i & 8191;
        int n = j >> 6, kp = j & 63;
        const float* W = m ? W2 : W1;
        float a = W[(2 * kp) * D + n];       // W^T[n][2kp]
        float b = W[(2 * kp + 1) * D + n];
        uint32_t h, l;
        bfsplit2(a, b, h, l);
        g_Wh[m][n * 64 + kp] = h;
        g_Wl[m][n * 64 + kp] = l;
    }
    if (i < N_EDGES) {
        int is64 = detect64(ep);
        int d = is64 ? (int)((const long long*)ep)[(long long)N_EDGES + i]
                     : ((const int*)ep)[N_EDGES + i];
        atomicAdd(&g_deg[d], 1);
    }
}

// ---------------- block-local exclusive scan + dinv --------------------------
__global__ void k_scan1() {
    __shared__ int s[SCAN_T];
    int i = blockIdx.x * SCAN_T + threadIdx.x;
    int v = (i < N_NODES) ? g_deg[i] : 0;
    if (i < N_NODES) g_dinv[i] = rsqrtf((float)v + 1.0f);  // +1 self loop
    s[threadIdx.x] = v;
    __syncthreads();
    #pragma unroll
    for (int off = 1; off < SCAN_T; off <<= 1) {
        int t = (threadIdx.x >= off) ? s[threadIdx.x - off] : 0;
        __syncthreads();
        s[threadIdx.x] += t;
        __syncthreads();
    }
    if (i < N_NODES) g_off[i] = s[threadIdx.x] - v;
    if (threadIdx.x == SCAN_T - 1) g_bsum[blockIdx.x] = s[SCAN_T - 1];
}

// ---------------- apply block offsets ----------------------------------------
__global__ void k_scan3() {
    __shared__ int s_boff;
    int b = blockIdx.x;
    int t = threadIdx.x;
    if (t == 0) s_boff = 0;
    __syncthreads();
    int partial = 0;
    for (int j = t; j < b; j += SCAN_T) partial += g_bsum[j];
    if (partial) atomicAdd(&s_boff, partial);
    __syncthreads();
    int i = b * SCAN_T + t;
    if (i < N_NODES) {
        int v = g_off[i] + s_boff;
        g_off[i] = v;
        g_cur[i] = v;
    }
}

// ---------------- CSR scatter (counting sort by dst, packed 8B entries) -----
__global__ void k_scatter(const void* ep) {
    int e = blockIdx.x * blockDim.x + threadIdx.x;
    if (e >= N_EDGES) return;
    int s = load_idx(ep, e);
    int d = load_idx(ep, (long long)N_EDGES + e);
    int pos = atomicAdd(&g_cur[d], 1);
    float w = g_dinv[s] * g_dinv[d];
    g_csr[pos] = make_uint2((uint32_t)s, __float_as_uint(w));
}

// ---------------- GEMM1: t1 = X @ W1 (bf16 3-term compensated) --------------
#define KS 136
#define GEMM_SMEM ((64 * KS * 2 + 128 * KS * 2) * 2)   // 104448 B

__global__ void __launch_bounds__(256) k_gemm(const float* __restrict__ X,
                                              const uint32_t* __restrict__ Wh,
                                              const uint32_t* __restrict__ Wl,
                                              float* __restrict__ Y) {
    extern __shared__ __nv_bfloat16 sm[];
    __nv_bfloat16* sAh = sm;
    __nv_bfloat16* sAl = sAh + 64 * KS;
    __nv_bfloat16* sWh = sAl + 64 * KS;
    __nv_bfloat16* sWl = sWh + 128 * KS;

    const int tid = threadIdx.x;
    const int rowBase = blockIdx.x * 64;

    // zero pool/cnt for this call's fused_ap
    int gtid = blockIdx.x * 256 + tid;
    if (gtid < N_GRAPHS * D) g_pool[gtid] = 0.0f;
    if (gtid < N_GRAPHS) g_cnt[gtid] = 0;

    const float4* X4 = (const float4*)X;
    #pragma unroll
    for (int i = tid; i < 64 * 32; i += 256) {
        int r = i >> 5, c4 = i & 31;
        float4 v = make_float4(0.f, 0.f, 0.f, 0.f);
        if (rowBase + r < N_NODES) v = X4[(size_t)(rowBase + r) * 32 + c4];
        uint32_t h01, l01, h23, l23;
        bfsplit2(v.x, v.y, h01, l01);
        bfsplit2(v.z, v.w, h23, l23);
        *(uint2*)&sAh[r * KS + c4 * 4] = make_uint2(h01, h23);
        *(uint2*)&sAl[r * KS + c4 * 4] = make_uint2(l01, l23);
    }
    const uint4* Wh4 = (const uint4*)Wh;
    const uint4* Wl4 = (const uint4*)Wl;
    uint32_t* sWh32 = (uint32_t*)sWh;
    uint32_t* sWl32 = (uint32_t*)sWl;
    #pragma unroll
    for (int i = tid; i < 128 * 16; i += 256) {
        int n = i >> 4, kq = i & 15;
        *(uint4*)&sWh32[n * (KS / 2) + kq * 4] = Wh4[i];
        *(uint4*)&sWl32[n * (KS / 2) + kq * 4] = Wl4[i];
    }
    __syncthreads();

    const int wid = tid >> 5, lane = tid & 31;
    const int g = lane >> 2, tg = lane & 3;
    const int mbase = (wid >> 2) * 32;
    const int nbase = (wid & 3) * 32;

    float acc[2][4][4];
    #pragma unroll
    for (int mf = 0; mf < 2; mf++)
        #pragma unroll
        for (int nf = 0; nf < 4; nf++)
            #pragma unroll
            for (int j = 0; j < 4; j++) acc[mf][nf][j] = 0.f;

    #pragma unroll 2
    for (int kc = 0; kc < 8; kc++) {
        const int kA = kc * 16 + 2 * tg;
        uint32_t ah[2][4], al[2][4];
        #pragma unroll
        for (int mf = 0; mf < 2; mf++) {
            int r = mbase + mf * 16 + g;
            ah[mf][0] = *(uint32_t*)&sAh[r * KS + kA];
            ah[mf][1] = *(uint32_t*)&sAh[(r + 8) * KS + kA];
            ah[mf][2] = *(uint32_t*)&sAh[r * KS + kA + 8];
            ah[mf][3] = *(uint32_t*)&sAh[(r + 8) * KS + kA + 8];
            al[mf][0] = *(uint32_t*)&sAl[r * KS + kA];
            al[mf][1] = *(uint32_t*)&sAl[(r + 8) * KS + kA];
            al[mf][2] = *(uint32_t*)&sAl[r * KS + kA + 8];
            al[mf][3] = *(uint32_t*)&sAl[(r + 8) * KS + kA + 8];
        }
        uint32_t bh[4][2], bl[4][2];
        #pragma unroll
        for (int nf = 0; nf < 4; nf++) {
            int n = nbase + nf * 8 + g;
            bh[nf][0] = *(uint32_t*)&sWh[n * KS + kA];
            bh[nf][1] = *(uint32_t*)&sWh[n * KS + kA + 8];
            bl[nf][0] = *(uint32_t*)&sWl[n * KS + kA];
            bl[nf][1] = *(uint32_t*)&sWl[n * KS + kA + 8];
        }
        #pragma unroll
        for (int mf = 0; mf < 2; mf++)
            #pragma unroll
            for (int nf = 0; nf < 4; nf++) {
                mma16(acc[mf][nf], ah[mf], bh[nf]);
                mma16(acc[mf][nf], ah[mf], bl[nf]);
                mma16(acc[mf][nf], al[mf], bh[nf]);
            }
    }

    #pragma unroll
    for (int mf = 0; mf < 2; mf++) {
        int row = rowBase + mbase + mf * 16 + g;
        #pragma unroll
        for (int nf = 0; nf < 4; nf++) {
            int col = nbase + nf * 8 + 2 * tg;
            if (row < N_NODES)
                *(float2*)&Y[(size_t)row * D + col] =
                    make_float2(acc[mf][nf][0], acc[mf][nf][1]);
            if (row + 8 < N_NODES)
                *(float2*)&Y[(size_t)(row + 8) * D + col] =
                    make_float2(acc[mf][nf][2], acc[mf][nf][3]);
        }
    }
}

// ---------------- FUSED A: h1 = relu(Â t1 + b1); t2 = h1 @ W2 ---------------
__global__ void __launch_bounds__(256) k_fused_ag(const float* __restrict__ T1,
                                                  const uint32_t* __restrict__ Wh,
                                                  const uint32_t* __restrict__ Wl,
                                                  const float* __restrict__ bias,
                                                  float* __restrict__ Y) {
    extern __shared__ __nv_bfloat16 sm[];
    __nv_bfloat16* sAh = sm;
    __nv_bfloat16* sAl = sAh + 64 * KS;
    __nv_bfloat16* sWh = sAl + 64 * KS;
    __nv_bfloat16* sWl = sWh + 128 * KS;

    const int tid = threadIdx.x;
    const int wid = tid >> 5, lane = tid & 31;
    const int rowBase = blockIdx.x * 64;

    // ---- W stage ----
    const uint4* Wh4 = (const uint4*)Wh;
    const uint4* Wl4 = (const uint4*)Wl;
    uint32_t* sWh32 = (uint32_t*)sWh;
    uint32_t* sWl32 = (uint32_t*)sWl;
    #pragma unroll
    for (int i = tid; i < 128 * 16; i += 256) {
        int n = i >> 4, kq = i & 15;
        *(uint4*)&sWh32[n * (KS / 2) + kq * 4] = Wh4[i];
        *(uint4*)&sWl32[n * (KS / 2) + kq * 4] = Wl4[i];
    }

    // ---- gather phase: each warp produces 8 rows, split to bf16 A tile ----
    const float4* h4 = (const float4*)T1;
    const float4 bvec = ((const float4*)bias)[lane];
    #pragma unroll
    for (int i = 0; i < 8; i++) {
        int r = wid * 8 + i;
        int node = rowBase + r;
        float4 v = make_float4(0.f, 0.f, 0.f, 0.f);
        if (node < N_NODES) v = gather_row(h4, node, lane, bvec);
        uint32_t h01, l01, h23, l23;
        bfsplit2(v.x, v.y, h01, l01);
        bfsplit2(v.z, v.w, h23, l23);
        *(uint2*)&sAh[r * KS + lane * 4] = make_uint2(h01, h23);
        *(uint2*)&sAl[r * KS + lane * 4] = make_uint2(l01, l23);
    }
    __syncthreads();

    // ---- MMA phase ----
    const int g = lane >> 2, tg = lane & 3;
    const int mbase = (wid >> 2) * 32;
    const int nbase = (wid & 3) * 32;

    float acc[2][4][4];
    #pragma unroll
    for (int mf = 0; mf < 2; mf++)
        #pragma unroll
        for (int nf = 0; nf < 4; nf++)
            #pragma unroll
            for (int j = 0; j < 4; j++) acc[mf][nf][j] = 0.f;

    #pragma unroll 2
    for (int kc = 0; kc < 8; kc++) {
        const int kA = kc * 16 + 2 * tg;
        uint32_t ah[2][4], al[2][4];
        #pragma unroll
        for (int mf = 0; mf < 2; mf++) {
            int r = mbase + mf * 16 + g;
            ah[mf][0] = *(uint32_t*)&sAh[r * KS + kA];
            ah[mf][1] = *(uint32_t*)&sAh[(r + 8) * KS + kA];
            ah[mf][2] = *(uint32_t*)&sAh[r * KS + kA + 8];
            ah[mf][3] = *(uint32_t*)&sAh[(r + 8) * KS + kA + 8];
            al[mf][0] = *(uint32_t*)&sAl[r * KS + kA];
            al[mf][1] = *(uint32_t*)&sAl[(r + 8) * KS + kA];
            al[mf][2] = *(uint32_t*)&sAl[r * KS + kA + 8];
            al[mf][3] = *(uint32_t*)&sAl[(r + 8) * KS + kA + 8];
        }
        uint32_t bh[4][2], bl[4][2];
        #pragma unroll
        for (int nf = 0; nf < 4; nf++) {
            int n = nbase + nf * 8 + g;
            bh[nf][0] = *(uint32_t*)&sWh[n * KS + kA];
            bh[nf][1] = *(uint32_t*)&sWh[n * KS + kA + 8];
            bl[nf][0] = *(uint32_t*)&sWl[n * KS + kA];
            bl[nf][1] = *(uint32_t*)&sWl[n * KS + kA + 8];
        }
        #pragma unroll
        for (int mf = 0; mf < 2; mf++)
            #pragma unroll
            for (int nf = 0; nf < 4; nf++) {
                mma16(acc[mf][nf], ah[mf], bh[nf]);
                mma16(acc[mf][nf], ah[mf], bl[nf]);
                mma16(acc[mf][nf], al[mf], bh[nf]);
            }
    }

    #pragma unroll
    for (int mf = 0; mf < 2; mf++) {
        int row = rowBase + mbase + mf * 16 + g;
        #pragma unroll
        for (int nf = 0; nf < 4; nf++) {
            int col = nbase + nf * 8 + 2 * tg;
            if (row < N_NODES)
                *(float2*)&Y[(size_t)row * D + col] =
                    make_float2(acc[mf][nf][0], acc[mf][nf][1]);
            if (row + 8 < N_NODES)
                *(float2*)&Y[(size_t)(row + 8) * D + col] =
                    make_float2(acc[mf][nf][2], acc[mf][nf][3]);
        }
    }
}

// ---------------- FUSED B: h2 = relu(Â t2 + b2); pool atomics ---------------
#define HS 132
__global__ void __launch_bounds__(256) k_fused_ap(const float* __restrict__ T2,
                                                  const float* __restrict__ bias,
                                                  const void* batchp) {
    __shared__ float sH[64 * HS];
    __shared__ int sg[64];

    const int tid = threadIdx.x;
    const int wid = tid >> 5, lane = tid & 31;
    const int rowBase = blockIdx.x * 64;
    const int n_here = min(64, N_NODES - rowBase);

    if (tid < 64 && rowBase + tid < N_NODES) {
        sg[tid] = load_idx(batchp, rowBase + tid);
        g_deg[rowBase + tid] = 0;            // prep next replay
    }

    const float4* h4 = (const float4*)T2;
    const float4 bvec = ((const float4*)bias)[lane];
    #pragma unroll
    for (int i = 0; i < 8; i++) {
        int r = wid * 8 + i;
        int node = rowBase + r;
        if (node < N_NODES) {
            float4 v = gather_row(h4, node, lane, bvec);
            *(float4*)&sH[r * HS + lane * 4] = v;
        }
    }
    __syncthreads();

    // ---- pool: run-length accumulate, rare atomics (batch sorted) ----
    if (tid < 128) {
        float acc = 0.f;
        int cur = sg[0];
        int runstart = 0;
        for (int n = 0; n < n_here; n++) {
            int g = sg[n];
            if (g != cur) {
                atomicAdd(&g_pool[cur * D + tid], acc);
                if (tid == 0) atomicAdd(&g_cnt[cur], n - runstart);
                acc = 0.f; cur = g; runstart = n;
            }
            acc += sH[n * HS + tid];
        }
        atomicAdd(&g_pool[cur * D + tid], acc);
        if (tid == 0) atomicAdd(&g_cnt[cur], n_here - runstart);
    }
}

// ---------------- final FC: out = relu( (pool/cnt) @ Wfc + bfc ) ------------
__global__ void k_fc(const float* __restrict__ Wfc,
                     const float* __restrict__ bfc,
                     float* __restrict__ out) {
    __shared__ float srow[D];
    int g = blockIdx.x;
    int t = threadIdx.x;
    float cnt = fmaxf((float)g_cnt[g], 1.0f);
    srow[t] = g_pool[g * D + t] / cnt;
    __syncthreads();
    float acc = bfc[t];
    #pragma unroll 4
    for (int k = 0; k < D; k++)
        acc = fmaf(srow[k], Wfc[k * D + t], acc);
    out[g * D + t] = fmaxf(acc, 0.f);
}

// ---------------- launch ----------------------------------------------------
extern "C" void kernel_launch(void* const* d_in, const int* in_sizes, int n_in,
                              void* d_out, int out_size) {
    const float* x    = (const float*)d_in[0];
    const void*  edge = d_in[1];
    const void*  batch= d_in[2];
    const float* W1   = (const float*)d_in[3];
    const float* b1   = (const float*)d_in[4];
    const float* W2   = (const float*)d_in[5];
    const float* b2   = (const float*)d_in[6];
    const float* Wfc  = (const float*)d_in[7];
    const float* bfc  = (const float*)d_in[8];
    float* out = (float*)d_out;

    void *pt1, *pt2, *pwh, *pwl;
    cudaGetSymbolAddress(&pt1, g_t1);
    cudaGetSymbolAddress(&pt2, g_t2);
    cudaGetSymbolAddress(&pwh, g_Wh);
    cudaGetSymbolAddress(&pwl, g_Wl);
    float* t1 = (float*)pt1;
    float* t2 = (float*)pt2;
    uint32_t* wh = (uint32_t*)pwh;
    uint32_t* wl = (uint32_t*)pwl;

    cudaFuncSetAttribute(k_gemm, cudaFuncAttributeMaxDynamicSharedMemorySize,
                         GEMM_SMEM);
    cudaFuncSetAttribute(k_fused_ag, cudaFuncAttributeMaxDynamicSharedMemorySize,
                         GEMM_SMEM);

    const int EB = (N_EDGES + 255) / 256;
    const int TILE_GRID = (N_NODES + 63) / 64;   // 1563

    // ---- preprocessing ----
    k_deg<<<EB, 256>>>(edge, W1, W2);
    k_scan1<<<NB, SCAN_T>>>();
    k_scan3<<<NB, SCAN_T>>>();
    k_scatter<<<EB, 256>>>(edge);

    // ---- layer 1 GEMM, fused agg1+GEMM2, fused agg2+pool, FC ----
    k_gemm<<<TILE_GRID, 256, GEMM_SMEM>>>(x, wh, wl, t1);
    k_fused_ag<<<TILE_GRID, 256, GEMM_SMEM>>>(t1, wh + D * 64, wl + D * 64, b1, t2);
    k_fused_ap<<<TILE_GRID, 256>>>(t2, b2, batch);
    k_fc<<<N_GRAPHS, D>>>(Wfc, bfc, out);
}

// round 7
// speedup vs baseline: 1.1994x; 1.1994x over previous
#include <cuda_runtime.h>
#include <cuda_bf16.h>
#include <cuda_fp16.h>
#include <cstdint>

#define N_NODES 100000
#define N_EDGES 1600000
#define N_GRAPHS 64
#define D 128

#define SCAN_T 1024
#define NB ((N_NODES + SCAN_T - 1) / SCAN_T)   // 98

// ---------------- scratch (device globals; no allocation allowed) ----------
__device__ __half g_t1[(size_t)N_NODES * D];  // X@W1, fp16 (gather fodder)
__device__ float  g_h1[(size_t)N_NODES * D];  // relu(A t1 + b1), fp32
__device__ __half g_t2[(size_t)N_NODES * D];  // h1@W2, fp16
__device__ int   g_deg[N_NODES];              // zeroed by k_fused_ap for next call
__device__ float g_dinv[N_NODES];
__device__ int   g_off[N_NODES + 1];
__device__ int   g_cur[N_NODES];
__device__ uint2 g_csr[N_EDGES];              // .x = src, .y = weight bits
__device__ int   g_bsum[NB];
__device__ float g_pool[N_GRAPHS * D];        // zeroed by k_gemm
__device__ int   g_cnt[N_GRAPHS];
__device__ int   g_is64;
__device__ uint32_t g_Wh[2][D * 64];          // W^T bf16-hi, packed pairs [n][k/2]
__device__ uint32_t g_Wl[2][D * 64];          // W^T bf16-lo

// ---------------- helpers ---------------------------------------------------
__device__ __forceinline__ int load_idx(const void* p, long long i) {
    if (g_is64) return (int)((const long long*)p)[i];
    return ((const int*)p)[i];
}

__device__ __forceinline__ int detect64(const void* ep) {
    const int* p = (const int*)ep;
    int is64 = 1;
    #pragma unroll
    for (int j = 0; j < 8; j++)
        if (p[2 * j + 1] != 0) is64 = 0;
    return is64;
}

// split two fp32 into packed bf16x2 hi + bf16x2 lo (Markidis)
__device__ __forceinline__ void bfsplit2(float a, float b,
                                         uint32_t& h, uint32_t& l) {
    __nv_bfloat162 hv = __float22bfloat162_rn(make_float2(a, b));
    float2 hf = __bfloat1622float2(hv);
    __nv_bfloat162 lv = __float22bfloat162_rn(make_float2(a - hf.x, b - hf.y));
    h = *reinterpret_cast<uint32_t*>(&hv);
    l = *reinterpret_cast<uint32_t*>(&lv);
}

__device__ __forceinline__ void mma16(float* c, const uint32_t* a,
                                      const uint32_t* b) {
    asm volatile(
        "mma.sync.aligned.m16n8k16.row.col.f32.bf16.bf16.f32 "
        "{%0,%1,%2,%3}, {%4,%5,%6,%7}, {%8,%9}, {%0,%1,%2,%3};"
        : "+f"(c[0]), "+f"(c[1]), "+f"(c[2]), "+f"(c[3])
        : "r"(a[0]), "r"(a[1]), "r"(a[2]), "r"(a[3]), "r"(b[0]), "r"(b[1]));
}

__device__ __forceinline__ float4 h4tof4(uint2 v) {
    float2 a = __half22float2(*reinterpret_cast<__half2*>(&v.x));
    float2 b = __half22float2(*reinterpret_cast<__half2*>(&v.y));
    return make_float4(a.x, a.y, b.x, b.y);
}

// gather one node row from fp16 features:
// relu( dinv^2*h[node] + sum_e w*h[src] + bias )
// lane covers features 4*lane..4*lane+3 (one uint2 = 4 halfs).
// 4 independent accumulator chains for MLP>=4.
__device__ __forceinline__ float4 gather_row16(const uint2* __restrict__ hp,
                                               int node, int lane,
                                               const float4 b) {
    float dii = g_dinv[node];
    float sw = dii * dii;
    float4 s = h4tof4(hp[(size_t)node * 32 + lane]);
    float4 acc[4];
    acc[0] = make_float4(s.x * sw, s.y * sw, s.z * sw, s.w * sw);
    acc[1] = make_float4(0.f, 0.f, 0.f, 0.f);
    acc[2] = acc[1];
    acc[3] = acc[1];

    int e = g_off[node];
    const int end = g_off[node + 1];
    for (; e + 3 < end; e += 4) {
        uint2 p[4];
        #pragma unroll
        for (int j = 0; j < 4; j++) p[j] = g_csr[e + j];
        uint2 raw[4];
        #pragma unroll
        for (int j = 0; j < 4; j++) raw[j] = hp[(size_t)p[j].x * 32 + lane];
        #pragma unroll
        for (int j = 0; j < 4; j++) {
            float w = __uint_as_float(p[j].y);
            float4 v = h4tof4(raw[j]);
            acc[j].x = fmaf(v.x, w, acc[j].x);
            acc[j].y = fmaf(v.y, w, acc[j].y);
            acc[j].z = fmaf(v.z, w, acc[j].z);
            acc[j].w = fmaf(v.w, w, acc[j].w);
        }
    }
    for (; e < end; e++) {
        uint2 p = g_csr[e];
        float w = __uint_as_float(p.y);
        float4 v = h4tof4(hp[(size_t)p.x * 32 + lane]);
        acc[0].x = fmaf(v.x, w, acc[0].x);
        acc[0].y = fmaf(v.y, w, acc[0].y);
        acc[0].z = fmaf(v.z, w, acc[0].z);
        acc[0].w = fmaf(v.w, w, acc[0].w);
    }
    float4 r;
    r.x = fmaxf(acc[0].x + acc[1].x + acc[2].x + acc[3].x + b.x, 0.f);
    r.y = fmaxf(acc[0].y + acc[1].y + acc[2].y + acc[3].y + b.y, 0.f);
    r.z = fmaxf(acc[0].z + acc[1].z + acc[2].z + acc[3].z + b.z, 0.f);
    r.w = fmaxf(acc[0].w + acc[1].w + acc[2].w + acc[3].w + b.w, 0.f);
    return r;
}

// ---------------- deg count + init (W split/transpose, dtype, off[N]) -------
__global__ void k_deg(const void* ep, const float* W1, const float* W2) {
    int i = blockIdx.x * blockDim.x + threadIdx.x;
    if (i == 0) {
        g_is64 = detect64(ep);
        g_off[N_NODES] = N_EDGES;
    }
    if (i < 2 * D * 64) {          // one u32-pair of W^T per thread
        int m = i >> 13;           // 0 -> W1, 1 -> W2
        int j = i & 8191;
        int n = j >> 6, kp = j & 63;
        const float* W = m ? W2 : W1;
        float a = W[(2 * kp) * D + n];       // W^T[n][2kp]
        float b = W[(2 * kp + 1) * D + n];
        uint32_t h, l;
        bfsplit2(a, b, h, l);
        g_Wh[m][n * 64 + kp] = h;
        g_Wl[m][n * 64 + kp] = l;
    }
    if (i < N_EDGES) {
        int is64 = detect64(ep);
        int d = is64 ? (int)((const long long*)ep)[(long long)N_EDGES + i]
                     : ((const int*)ep)[N_EDGES + i];
        atomicAdd(&g_deg[d], 1);
    }
}

// ---------------- block-local exclusive scan + dinv --------------------------
__global__ void k_scan1() {
    __shared__ int s[SCAN_T];
    int i = blockIdx.x * SCAN_T + threadIdx.x;
    int v = (i < N_NODES) ? g_deg[i] : 0;
    if (i < N_NODES) g_dinv[i] = rsqrtf((float)v + 1.0f);  // +1 self loop
    s[threadIdx.x] = v;
    __syncthreads();
    #pragma unroll
    for (int off = 1; off < SCAN_T; off <<= 1) {
        int t = (threadIdx.x >= off) ? s[threadIdx.x - off] : 0;
        __syncthreads();
        s[threadIdx.x] += t;
        __syncthreads();
    }
    if (i < N_NODES) g_off[i] = s[threadIdx.x] - v;
    if (threadIdx.x == SCAN_T - 1) g_bsum[blockIdx.x] = s[SCAN_T - 1];
}

// ---------------- apply block offsets ----------------------------------------
__global__ void k_scan3() {
    __shared__ int s_boff;
    int b = blockIdx.x;
    int t = threadIdx.x;
    if (t == 0) s_boff = 0;
    __syncthreads();
    int partial = 0;
    for (int j = t; j < b; j += SCAN_T) partial += g_bsum[j];
    if (partial) atomicAdd(&s_boff, partial);
    __syncthreads();
    int i = b * SCAN_T + t;
    if (i < N_NODES) {
        int v = g_off[i] + s_boff;
        g_off[i] = v;
        g_cur[i] = v;
    }
}

// ---------------- CSR scatter (counting sort by dst, packed 8B entries) -----
__global__ void k_scatter(const void* ep) {
    int e = blockIdx.x * blockDim.x + threadIdx.x;
    if (e >= N_EDGES) return;
    int s = load_idx(ep, e);
    int d = load_idx(ep, (long long)N_EDGES + e);
    int pos = atomicAdd(&g_cur[d], 1);
    float w = g_dinv[s] * g_dinv[d];
    g_csr[pos] = make_uint2((uint32_t)s, __float_as_uint(w));
}

// ---------------- GEMM: Y16 = X @ W (bf16 3-term compensated, fp16 out) -----
#define KS 136
#define GEMM_SMEM ((64 * KS * 2 + 128 * KS * 2) * 2)   // 104448 B

__global__ void __launch_bounds__(256) k_gemm(const float* __restrict__ X,
                                              const uint32_t* __restrict__ Wh,
                                              const uint32_t* __restrict__ Wl,
                                              __half* __restrict__ Y16) {
    extern __shared__ __nv_bfloat16 sm[];
    __nv_bfloat16* sAh = sm;
    __nv_bfloat16* sAl = sAh + 64 * KS;
    __nv_bfloat16* sWh = sAl + 64 * KS;
    __nv_bfloat16* sWl = sWh + 128 * KS;

    const int tid = threadIdx.x;
    const int rowBase = blockIdx.x * 64;

    // zero pool/cnt for this call's fused_ap (idempotent: runs pre-pool)
    int gtid = blockIdx.x * 256 + tid;
    if (gtid < N_GRAPHS * D) g_pool[gtid] = 0.0f;
    if (gtid < N_GRAPHS) g_cnt[gtid] = 0;

    const float4* X4 = (const float4*)X;
    #pragma unroll
    for (int i = tid; i < 64 * 32; i += 256) {
        int r = i >> 5, c4 = i & 31;
        float4 v = make_float4(0.f, 0.f, 0.f, 0.f);
        if (rowBase + r < N_NODES) v = X4[(size_t)(rowBase + r) * 32 + c4];
        uint32_t h01, l01, h23, l23;
        bfsplit2(v.x, v.y, h01, l01);
        bfsplit2(v.z, v.w, h23, l23);
        *(uint2*)&sAh[r * KS + c4 * 4] = make_uint2(h01, h23);
        *(uint2*)&sAl[r * KS + c4 * 4] = make_uint2(l01, l23);
    }
    const uint4* Wh4 = (const uint4*)Wh;
    const uint4* Wl4 = (const uint4*)Wl;
    uint32_t* sWh32 = (uint32_t*)sWh;
    uint32_t* sWl32 = (uint32_t*)sWl;
    #pragma unroll
    for (int i = tid; i < 128 * 16; i += 256) {
        int n = i >> 4, kq = i & 15;
        *(uint4*)&sWh32[n * (KS / 2) + kq * 4] = Wh4[i];
        *(uint4*)&sWl32[n * (KS / 2) + kq * 4] = Wl4[i];
    }
    __syncthreads();

    const int wid = tid >> 5, lane = tid & 31;
    const int g = lane >> 2, tg = lane & 3;
    const int mbase = (wid >> 2) * 32;
    const int nbase = (wid & 3) * 32;

    float acc[2][4][4];
    #pragma unroll
    for (int mf = 0; mf < 2; mf++)
        #pragma unroll
        for (int nf = 0; nf < 4; nf++)
            #pragma unroll
            for (int j = 0; j < 4; j++) acc[mf][nf][j] = 0.f;

    #pragma unroll 2
    for (int kc = 0; kc < 8; kc++) {
        const int kA = kc * 16 + 2 * tg;
        uint32_t ah[2][4], al[2][4];
        #pragma unroll
        for (int mf = 0; mf < 2; mf++) {
            int r = mbase + mf * 16 + g;
            ah[mf][0] = *(uint32_t*)&sAh[r * KS + kA];
            ah[mf][1] = *(uint32_t*)&sAh[(r + 8) * KS + kA];
            ah[mf][2] = *(uint32_t*)&sAh[r * KS + kA + 8];
            ah[mf][3] = *(uint32_t*)&sAh[(r + 8) * KS + kA + 8];
            al[mf][0] = *(uint32_t*)&sAl[r * KS + kA];
            al[mf][1] = *(uint32_t*)&sAl[(r + 8) * KS + kA];
            al[mf][2] = *(uint32_t*)&sAl[r * KS + kA + 8];
            al[mf][3] = *(uint32_t*)&sAl[(r + 8) * KS + kA + 8];
        }
        uint32_t bh[4][2], bl[4][2];
        #pragma unroll
        for (int nf = 0; nf < 4; nf++) {
            int n = nbase + nf * 8 + g;
            bh[nf][0] = *(uint32_t*)&sWh[n * KS + kA];
            bh[nf][1] = *(uint32_t*)&sWh[n * KS + kA + 8];
            bl[nf][0] = *(uint32_t*)&sWl[n * KS + kA];
            bl[nf][1] = *(uint32_t*)&sWl[n * KS + kA + 8];
        }
        #pragma unroll
        for (int mf = 0; mf < 2; mf++)
            #pragma unroll
            for (int nf = 0; nf < 4; nf++) {
                mma16(acc[mf][nf], ah[mf], bh[nf]);
                mma16(acc[mf][nf], ah[mf], bl[nf]);
                mma16(acc[mf][nf], al[mf], bh[nf]);
            }
    }

    // epilogue: fp16 output (gather fodder)
    #pragma unroll
    for (int mf = 0; mf < 2; mf++) {
        int row = rowBase + mbase + mf * 16 + g;
        #pragma unroll
        for (int nf = 0; nf < 4; nf++) {
            int col = nbase + nf * 8 + 2 * tg;
            if (row < N_NODES) {
                __half2 h = __float22half2_rn(
                    make_float2(acc[mf][nf][0], acc[mf][nf][1]));
                *(__half2*)&Y16[(size_t)row * D + col] = h;
            }
            if (row + 8 < N_NODES) {
                __half2 h = __float22half2_rn(
                    make_float2(acc[mf][nf][2], acc[mf][nf][3]));
                *(__half2*)&Y16[(size_t)(row + 8) * D + col] = h;
            }
        }
    }
}

// ---------------- agg1: h1 = relu(A t1 + b1), fp16 in, fp32 out -------------
__global__ void k_agg(const __half* __restrict__ hin,
                      float* __restrict__ hout,
                      const float* __restrict__ bias) {
    int node = (blockIdx.x * blockDim.x + threadIdx.x) >> 5;
    if (node >= N_NODES) return;
    int lane = threadIdx.x & 31;

    const uint2* hp = (const uint2*)hin;
    const float4 b = ((const float4*)bias)[lane];
    float4 r = gather_row16(hp, node, lane, b);
    ((float4*)hout)[(size_t)node * 32 + lane] = r;
}

// ---------------- FUSED B: h2 = relu(A t2 + b2); pool atomics ---------------
#define HS 132
__global__ void __launch_bounds__(256) k_fused_ap(const __half* __restrict__ T2,
                                                  const float* __restrict__ bias,
                                                  const void* batchp) {
    __shared__ float sH[64 * HS];
    __shared__ int sg[64];

    const int tid = threadIdx.x;
    const int wid = tid >> 5, lane = tid & 31;
    const int rowBase = blockIdx.x * 64;
    const int n_here = min(64, N_NODES - rowBase);

    if (tid < 64 && rowBase + tid < N_NODES) {
        sg[tid] = load_idx(batchp, rowBase + tid);
        g_deg[rowBase + tid] = 0;            // prep next replay
    }

    const uint2* hp = (const uint2*)T2;
    const float4 bvec = ((const float4*)bias)[lane];
    #pragma unroll
    for (int i = 0; i < 8; i++) {
        int r = wid * 8 + i;
        int node = rowBase + r;
        if (node < N_NODES) {
            float4 v = gather_row16(hp, node, lane, bvec);
            *(float4*)&sH[r * HS + lane * 4] = v;
        }
    }
    __syncthreads();

    // ---- pool: run-length accumulate, rare atomics (batch sorted) ----
    if (tid < 128) {
        float acc = 0.f;
        int cur = sg[0];
        int runstart = 0;
        for (int n = 0; n < n_here; n++) {
            int g = sg[n];
            if (g != cur) {
                atomicAdd(&g_pool[cur * D + tid], acc);
                if (tid == 0) atomicAdd(&g_cnt[cur], n - runstart);
                acc = 0.f; cur = g; runstart = n;
            }
            acc += sH[n * HS + tid];
        }
        atomicAdd(&g_pool[cur * D + tid], acc);
        if (tid == 0) atomicAdd(&g_cnt[cur], n_here - runstart);
    }
}

// ---------------- final FC: out = relu( (pool/cnt) @ Wfc + bfc ) ------------
__global__ void k_fc(const float* __restrict__ Wfc,
                     const float* __restrict__ bfc,
                     float* __restrict__ out) {
    __shared__ float srow[D];
    int g = blockIdx.x;
    int t = threadIdx.x;
    float cnt = fmaxf((float)g_cnt[g], 1.0f);
    srow[t] = g_pool[g * D + t] / cnt;
    __syncthreads();
    float acc = bfc[t];
    #pragma unroll 4
    for (int k = 0; k < D; k++)
        acc = fmaf(srow[k], Wfc[k * D + t], acc);
    out[g * D + t] = fmaxf(acc, 0.f);
}

// ---------------- launch ----------------------------------------------------
extern "C" void kernel_launch(void* const* d_in, const int* in_sizes, int n_in,
                              void* d_out, int out_size) {
    const float* x    = (const float*)d_in[0];
    const void*  edge = d_in[1];
    const void*  batch= d_in[2];
    const float* W1   = (const float*)d_in[3];
    const float* b1   = (const float*)d_in[4];
    const float* W2   = (const float*)d_in[5];
    const float* b2   = (const float*)d_in[6];
    const float* Wfc  = (const float*)d_in[7];
    const float* bfc  = (const float*)d_in[8];
    float* out = (float*)d_out;

    void *pt1, *pt2, *ph1, *pwh, *pwl;
    cudaGetSymbolAddress(&pt1, g_t1);
    cudaGetSymbolAddress(&pt2, g_t2);
    cudaGetSymbolAddress(&ph1, g_h1);
    cudaGetSymbolAddress(&pwh, g_Wh);
    cudaGetSymbolAddress(&pwl, g_Wl);
    __half* t1 = (__half*)pt1;
    __half* t2 = (__half*)pt2;
    float* h1 = (float*)ph1;
    uint32_t* wh = (uint32_t*)pwh;
    uint32_t* wl = (uint32_t*)pwl;

    cudaFuncSetAttribute(k_gemm, cudaFuncAttributeMaxDynamicSharedMemorySize,
                         GEMM_SMEM);

    const int EB = (N_EDGES + 255) / 256;
    const int TILE_GRID = (N_NODES + 63) / 64;          // 1563
    const int AGG_BLOCKS = (N_NODES * 32 + 255) / 256;  // 12500

    // ---- preprocessing ----
    k_deg<<<EB, 256>>>(edge, W1, W2);
    k_scan1<<<NB, SCAN_T>>>();
    k_scan3<<<NB, SCAN_T>>>();
    k_scatter<<<EB, 256>>>(edge);

    // ---- layer 1: t1 = X@W1 (fp16 out); h1 = relu(A t1 + b1) (fp32) ----
    k_gemm<<<TILE_GRID, 256, GEMM_SMEM>>>(x, wh, wl, t1);
    k_agg<<<AGG_BLOCKS, 256>>>(t1, h1, b1);

    // ---- layer 2: t2 = h1@W2 (fp16 out); fused agg2 + pool ----
    k_gemm<<<TILE_GRID, 256, GEMM_SMEM>>>(h1, wh + D * 64, wl + D * 64, t2);
    k_fused_ap<<<TILE_GRID, 256>>>(t2, b2, batch);

    // ---- fc ----
    k_fc<<<N_GRAPHS, D>>>(Wfc, bfc, out);
}

// round 8
// speedup vs baseline: 1.2153x; 1.0133x over previous
#include <cuda_runtime.h>
#include <cuda_bf16.h>
#include <cuda_fp16.h>
#include <cstdint>

#define N_NODES 100000
#define N_EDGES 1600000
#define N_GRAPHS 64
#define D 128

#define SCAN_T 1024
#define NB ((N_NODES + SCAN_T - 1) / SCAN_T)   // 98

// ---------------- scratch (device globals; no allocation allowed) ----------
__device__ __half g_t1[(size_t)N_NODES * D];  // X@W1, fp16
__device__ __half g_h1[(size_t)N_NODES * D];  // relu(A t1 + b1), fp16
__device__ __half g_t2[(size_t)N_NODES * D];  // h1@W2, fp16
__device__ int   g_deg[N_NODES];              // zeroed by k_fused_ap for next call
__device__ float g_dinv[N_NODES];
__device__ int   g_off[N_NODES + 1];
__device__ int   g_cur[N_NODES];
__device__ uint2 g_csr[N_EDGES];              // .x = src, .y = weight bits
__device__ int   g_bsum[NB];                  // re-armed to -1 by k_deg
__device__ float g_pool[N_GRAPHS * D];        // zeroed by k_gemm
__device__ int   g_cnt[N_GRAPHS];
__device__ int   g_is64;
__device__ uint32_t g_Wh[2][D * 64];          // W^T bf16-hi, packed pairs [n][k/2]
__device__ uint32_t g_Wl[2][D * 64];          // W^T bf16-lo

// ---------------- helpers ---------------------------------------------------
__device__ __forceinline__ int load_idx(const void* p, long long i) {
    if (g_is64) return (int)((const long long*)p)[i];
    return ((const int*)p)[i];
}

__device__ __forceinline__ int detect64(const void* ep) {
    const int* p = (const int*)ep;
    int is64 = 1;
    #pragma unroll
    for (int j = 0; j < 8; j++)
        if (p[2 * j + 1] != 0) is64 = 0;
    return is64;
}

// split two fp32 into packed bf16x2 hi + bf16x2 lo (Markidis)
__device__ __forceinline__ void bfsplit2(float a, float b,
                                         uint32_t& h, uint32_t& l) {
    __nv_bfloat162 hv = __float22bfloat162_rn(make_float2(a, b));
    float2 hf = __bfloat1622float2(hv);
    __nv_bfloat162 lv = __float22bfloat162_rn(make_float2(a - hf.x, b - hf.y));
    h = *reinterpret_cast<uint32_t*>(&hv);
    l = *reinterpret_cast<uint32_t*>(&lv);
}

__device__ __forceinline__ void mma16(float* c, const uint32_t* a,
                                      const uint32_t* b) {
    asm volatile(
        "mma.sync.aligned.m16n8k16.row.col.f32.bf16.bf16.f32 "
        "{%0,%1,%2,%3}, {%4,%5,%6,%7}, {%8,%9}, {%0,%1,%2,%3};"
        : "+f"(c[0]), "+f"(c[1]), "+f"(c[2]), "+f"(c[3])
        : "r"(a[0]), "r"(a[1]), "r"(a[2]), "r"(a[3]), "r"(b[0]), "r"(b[1]));
}

__device__ __forceinline__ float4 h4tof4(uint2 v) {
    float2 a = __half22float2(*reinterpret_cast<__half2*>(&v.x));
    float2 b = __half22float2(*reinterpret_cast<__half2*>(&v.y));
    return make_float4(a.x, a.y, b.x, b.y);
}

__device__ __forceinline__ uint2 f4toh4(float4 v) {
    __half2 a = __float22half2_rn(make_float2(v.x, v.y));
    __half2 b = __float22half2_rn(make_float2(v.z, v.w));
    uint2 o;
    o.x = *reinterpret_cast<uint32_t*>(&a);
    o.y = *reinterpret_cast<uint32_t*>(&b);
    return o;
}

// gather one node row from fp16 features:
// relu( dinv^2*h[node] + sum_e w*h[src] + bias )
__device__ __forceinline__ float4 gather_row16(const uint2* __restrict__ hp,
                                               int node, int lane,
                                               const float4 b) {
    float dii = g_dinv[node];
    float sw = dii * dii;
    float4 s = h4tof4(hp[(size_t)node * 32 + lane]);
    float4 acc[4];
    acc[0] = make_float4(s.x * sw, s.y * sw, s.z * sw, s.w * sw);
    acc[1] = make_float4(0.f, 0.f, 0.f, 0.f);
    acc[2] = acc[1];
    acc[3] = acc[1];

    int e = g_off[node];
    const int end = g_off[node + 1];
    for (; e + 3 < end; e += 4) {
        uint2 p[4];
        #pragma unroll
        for (int j = 0; j < 4; j++) p[j] = g_csr[e + j];
        uint2 raw[4];
        #pragma unroll
        for (int j = 0; j < 4; j++) raw[j] = hp[(size_t)p[j].x * 32 + lane];
        #pragma unroll
        for (int j = 0; j < 4; j++) {
            float w = __uint_as_float(p[j].y);
            float4 v = h4tof4(raw[j]);
            acc[j].x = fmaf(v.x, w, acc[j].x);
            acc[j].y = fmaf(v.y, w, acc[j].y);
            acc[j].z = fmaf(v.z, w, acc[j].z);
            acc[j].w = fmaf(v.w, w, acc[j].w);
        }
    }
    for (; e < end; e++) {
        uint2 p = g_csr[e];
        float w = __uint_as_float(p.y);
        float4 v = h4tof4(hp[(size_t)p.x * 32 + lane]);
        acc[0].x = fmaf(v.x, w, acc[0].x);
        acc[0].y = fmaf(v.y, w, acc[0].y);
        acc[0].z = fmaf(v.z, w, acc[0].z);
        acc[0].w = fmaf(v.w, w, acc[0].w);
    }
    float4 r;
    r.x = fmaxf(acc[0].x + acc[1].x + acc[2].x + acc[3].x + b.x, 0.f);
    r.y = fmaxf(acc[0].y + acc[1].y + acc[2].y + acc[3].y + b.y, 0.f);
    r.z = fmaxf(acc[0].z + acc[1].z + acc[2].z + acc[3].z + b.z, 0.f);
    r.w = fmaxf(acc[0].w + acc[1].w + acc[2].w + acc[3].w + b.w, 0.f);
    return r;
}

// ---------------- deg count + init (W split, dtype, off[N], scan sentinel) --
__global__ void k_deg(const void* ep, const float* W1, const float* W2) {
    int i = blockIdx.x * blockDim.x + threadIdx.x;
    if (i == 0) {
        g_is64 = detect64(ep);
        g_off[N_NODES] = N_EDGES;
    }
    if (i < NB) g_bsum[i] = -1;    // arm scan publication sentinel
    if (i < 2 * D * 64) {          // one u32-pair of W^T per thread
        int m = i >> 13;           // 0 -> W1, 1 -> W2
        int j = i & 8191;
        int n = j >> 6, kp = j & 63;
        const float* W = m ? W2 : W1;
        float a = W[(2 * kp) * D + n];       // W^T[n][2kp]
        float b = W[(2 * kp + 1) * D + n];
        uint32_t h, l;
        bfsplit2(a, b, h, l);
        g_Wh[m][n * 64 + kp] = h;
        g_Wl[m][n * 64 + kp] = l;
    }
    if (i < N_EDGES) {
        int is64 = detect64(ep);
        int d = is64 ? (int)((const long long*)ep)[(long long)N_EDGES + i]
                     : ((const int*)ep)[N_EDGES + i];
        atomicAdd(&g_deg[d], 1);
    }
}

// ---------------- single-pass scan (98 blocks = 1 wave; spin publication) ---
__global__ void k_scan() {
    __shared__ int s[SCAN_T];
    __shared__ int s_boff;
    const int b = blockIdx.x;
    const int t = threadIdx.x;
    const int i = b * SCAN_T + t;
    int v = (i < N_NODES) ? g_deg[i] : 0;
    if (i < N_NODES) g_dinv[i] = rsqrtf((float)v + 1.0f);  // +1 self loop
    s[t] = v;
    if (t == 0) s_boff = 0;
    __syncthreads();
    #pragma unroll
    for (int off = 1; off < SCAN_T; off <<= 1) {
        int u = (t >= off) ? s[t - off] : 0;
        __syncthreads();
        s[t] += u;
        __syncthreads();
    }
    // publish block total (volatile store; value IS the data)
    if (t == SCAN_T - 1)
        ((volatile int*)g_bsum)[b] = s[SCAN_T - 1];
    // consume earlier block totals (b <= 97 < blockDim)
    if (t < b) {
        int val;
        do { val = ((volatile int*)g_bsum)[t]; } while (val < 0);
        atomicAdd(&s_boff, val);
    }
    __syncthreads();
    if (i < N_NODES) {
        int off = s[t] - v + s_boff;   // exclusive prefix + block offset
        g_off[i] = off;
        g_cur[i] = off;
    }
}

// ---------------- CSR scatter (counting sort by dst, packed 8B entries) -----
__global__ void k_scatter(const void* ep) {
    int e = blockIdx.x * blockDim.x + threadIdx.x;
    if (e >= N_EDGES) return;
    int s = load_idx(ep, e);
    int d = load_idx(ep, (long long)N_EDGES + e);
    int pos = atomicAdd(&g_cur[d], 1);
    float w = g_dinv[s] * g_dinv[d];
    g_csr[pos] = make_uint2((uint32_t)s, __float_as_uint(w));
}

// ---------------- GEMM: Y16 = X @ W (bf16 3-term compensated, fp16 out) -----
// CTA: 256 thr; stages W once, then SUBT 64-row sub-tiles (W L2 traffic /SUBT).
#define KS 136
#define SUBT 2
#define GEMM_SMEM ((64 * KS * 2 + 128 * KS * 2) * 2)   // 104448 B

template <bool HALF_IN>
__global__ void __launch_bounds__(256) k_gemm(const void* __restrict__ Xv,
                                              const uint32_t* __restrict__ Wh,
                                              const uint32_t* __restrict__ Wl,
                                              __half* __restrict__ Y16) {
    extern __shared__ __nv_bfloat16 sm[];
    __nv_bfloat16* sAh = sm;
    __nv_bfloat16* sAl = sAh + 64 * KS;
    __nv_bfloat16* sWh = sAl + 64 * KS;
    __nv_bfloat16* sWl = sWh + 128 * KS;

    const int tid = threadIdx.x;
    const int rowBase0 = blockIdx.x * (64 * SUBT);

    // zero pool/cnt for this call's fused_ap (idempotent)
    int gtid = blockIdx.x * 256 + tid;
    if (gtid < N_GRAPHS * D) g_pool[gtid] = 0.0f;
    if (gtid < N_GRAPHS) g_cnt[gtid] = 0;

    // ---- stage W once ----
    const uint4* Wh4 = (const uint4*)Wh;
    const uint4* Wl4 = (const uint4*)Wl;
    uint32_t* sWh32 = (uint32_t*)sWh;
    uint32_t* sWl32 = (uint32_t*)sWl;
    #pragma unroll
    for (int i = tid; i < 128 * 16; i += 256) {
        int n = i >> 4, kq = i & 15;
        *(uint4*)&sWh32[n * (KS / 2) + kq * 4] = Wh4[i];
        *(uint4*)&sWl32[n * (KS / 2) + kq * 4] = Wl4[i];
    }

    const int wid = tid >> 5, lane = tid & 31;
    const int g = lane >> 2, tg = lane & 3;
    const int mbase = (wid >> 2) * 32;
    const int nbase = (wid & 3) * 32;

    for (int st = 0; st < SUBT; st++) {
        const int rowBase = rowBase0 + st * 64;
        if (st) __syncthreads();   // prior sub-tile's MMA reads of sA done

        // ---- stage A sub-tile ----
        #pragma unroll
        for (int i = tid; i < 64 * 32; i += 256) {
            int r = i >> 5, c4 = i & 31;
            float4 v = make_float4(0.f, 0.f, 0.f, 0.f);
            if (rowBase + r < N_NODES) {
                if (HALF_IN)
                    v = h4tof4(((const uint2*)Xv)[(size_t)(rowBase + r) * 32 + c4]);
                else
                    v = ((const float4*)Xv)[(size_t)(rowBase + r) * 32 + c4];
            }
            uint32_t h01, l01, h23, l23;
            bfsplit2(v.x, v.y, h01, l01);
            bfsplit2(v.z, v.w, h23, l23);
            *(uint2*)&sAh[r * KS + c4 * 4] = make_uint2(h01, h23);
            *(uint2*)&sAl[r * KS + c4 * 4] = make_uint2(l01, l23);
        }
        __syncthreads();

        float acc[2][4][4];
        #pragma unroll
        for (int mf = 0; mf < 2; mf++)
            #pragma unroll
            for (int nf = 0; nf < 4; nf++)
                #pragma unroll
                for (int j = 0; j < 4; j++) acc[mf][nf][j] = 0.f;

        #pragma unroll 2
        for (int kc = 0; kc < 8; kc++) {
            const int kA = kc * 16 + 2 * tg;
            uint32_t ah[2][4], al[2][4];
            #pragma unroll
            for (int mf = 0; mf < 2; mf++) {
                int r = mbase + mf * 16 + g;
                ah[mf][0] = *(uint32_t*)&sAh[r * KS + kA];
                ah[mf][1] = *(uint32_t*)&sAh[(r + 8) * KS + kA];
                ah[mf][2] = *(uint32_t*)&sAh[r * KS + kA + 8];
                ah[mf][3] = *(uint32_t*)&sAh[(r + 8) * KS + kA + 8];
                al[mf][0] = *(uint32_t*)&sAl[r * KS + kA];
                al[mf][1] = *(uint32_t*)&sAl[(r + 8) * KS + kA];
                al[mf][2] = *(uint32_t*)&sAl[r * KS + kA + 8];
                al[mf][3] = *(uint32_t*)&sAl[(r + 8) * KS + kA + 8];
            }
            uint32_t bh[4][2], bl[4][2];
            #pragma unroll
            for (int nf = 0; nf < 4; nf++) {
                int n = nbase + nf * 8 + g;
                bh[nf][0] = *(uint32_t*)&sWh[n * KS + kA];
                bh[nf][1] = *(uint32_t*)&sWh[n * KS + kA + 8];
                bl[nf][0] = *(uint32_t*)&sWl[n * KS + kA];
                bl[nf][1] = *(uint32_t*)&sWl[n * KS + kA + 8];
            }
            #pragma unroll
            for (int mf = 0; mf < 2; mf++)
                #pragma unroll
                for (int nf = 0; nf < 4; nf++) {
                    mma16(acc[mf][nf], ah[mf], bh[nf]);
                    mma16(acc[mf][nf], ah[mf], bl[nf]);
                    mma16(acc[mf][nf], al[mf], bh[nf]);
                }
        }

        // ---- epilogue: fp16 out ----
        #pragma unroll
        for (int mf = 0; mf < 2; mf++) {
            int row = rowBase + mbase + mf * 16 + g;
            #pragma unroll
            for (int nf = 0; nf < 4; nf++) {
                int col = nbase + nf * 8 + 2 * tg;
                if (row < N_NODES) {
                    __half2 h = __float22half2_rn(
                        make_float2(acc[mf][nf][0], acc[mf][nf][1]));
                    *(__half2*)&Y16[(size_t)row * D + col] = h;
                }
                if (row + 8 < N_NODES) {
                    __half2 h = __float22half2_rn(
                        make_float2(acc[mf][nf][2], acc[mf][nf][3]));
                    *(__half2*)&Y16[(size_t)(row + 8) * D + col] = h;
                }
            }
        }
    }
}

// ---------------- agg1: h1 = relu(A t1 + b1), fp16 in/out -------------------
__global__ void k_agg(const __half* __restrict__ hin,
                      __half* __restrict__ hout,
                      const float* __restrict__ bias) {
    int node = (blockIdx.x * blockDim.x + threadIdx.x) >> 5;
    if (node >= N_NODES) return;
    int lane = threadIdx.x & 31;

    const uint2* hp = (const uint2*)hin;
    const float4 b = ((const float4*)bias)[lane];
    float4 r = gather_row16(hp, node, lane, b);
    ((uint2*)hout)[(size_t)node * 32 + lane] = f4toh4(r);
}

// ---------------- FUSED B: h2 = relu(A t2 + b2); pool atomics ---------------
#define HS 132
__global__ void __launch_bounds__(256) k_fused_ap(const __half* __restrict__ T2,
                                                  const float* __restrict__ bias,
                                                  const void* batchp) {
    __shared__ float sH[64 * HS];
    __shared__ int sg[64];

    const int tid = threadIdx.x;
    const int wid = tid >> 5, lane = tid & 31;
    const int rowBase = blockIdx.x * 64;
    const int n_here = min(64, N_NODES - rowBase);

    if (tid < 64 && rowBase + tid < N_NODES) {
        sg[tid] = load_idx(batchp, rowBase + tid);
        g_deg[rowBase + tid] = 0;            // prep next replay
    }

    const uint2* hp = (const uint2*)T2;
    const float4 bvec = ((const float4*)bias)[lane];
    #pragma unroll
    for (int i = 0; i < 8; i++) {
        int r = wid * 8 + i;
        int node = rowBase + r;
        if (node < N_NODES) {
            float4 v = gather_row16(hp, node, lane, bvec);
            *(float4*)&sH[r * HS + lane * 4] = v;
        }
    }
    __syncthreads();

    // ---- pool: run-length accumulate, rare atomics (batch sorted) ----
    if (tid < 128) {
        float acc = 0.f;
        int cur = sg[0];
        int runstart = 0;
        for (int n = 0; n < n_here; n++) {
            int g = sg[n];
            if (g != cur) {
                atomicAdd(&g_pool[cur * D + tid], acc);
                if (tid == 0) atomicAdd(&g_cnt[cur], n - runstart);
                acc = 0.f; cur = g; runstart = n;
            }
            acc += sH[n * HS + tid];
        }
        atomicAdd(&g_pool[cur * D + tid], acc);
        if (tid == 0) atomicAdd(&g_cnt[cur], n_here - runstart);
    }
}

// ---------------- final FC: out = relu( (pool/cnt) @ Wfc + bfc ) ------------
__global__ void k_fc(const float* __restrict__ Wfc,
                     const float* __restrict__ bfc,
                     float* __restrict__ out) {
    __shared__ float srow[D];
    int g = blockIdx.x;
    int t = threadIdx.x;
    float cnt = fmaxf((float)g_cnt[g], 1.0f);
    srow[t] = g_pool[g * D + t] / cnt;
    __syncthreads();
    float acc = bfc[t];
    #pragma unroll 4
    for (int k = 0; k < D; k++)
        acc = fmaf(srow[k], Wfc[k * D + t], acc);
    out[g * D + t] = fmaxf(acc, 0.f);
}

// ---------------- launch ----------------------------------------------------
extern "C" void kernel_launch(void* const* d_in, const int* in_sizes, int n_in,
                              void* d_out, int out_size) {
    const float* x    = (const float*)d_in[0];
    const void*  edge = d_in[1];
    const void*  batch= d_in[2];
    const float* W1   = (const float*)d_in[3];
    const float* b1   = (const float*)d_in[4];
    const float* W2   = (const float*)d_in[5];
    const float* b2   = (const float*)d_in[6];
    const float* Wfc  = (const float*)d_in[7];
    const float* bfc  = (const float*)d_in[8];
    float* out = (float*)d_out;

    void *pt1, *pt2, *ph1, *pwh, *pwl;
    cudaGetSymbolAddress(&pt1, g_t1);
    cudaGetSymbolAddress(&pt2, g_t2);
    cudaGetSymbolAddress(&ph1, g_h1);
    cudaGetSymbolAddress(&pwh, g_Wh);
    cudaGetSymbolAddress(&pwl, g_Wl);
    __half* t1 = (__half*)pt1;
    __half* t2 = (__half*)pt2;
    __half* h1 = (__half*)ph1;
    uint32_t* wh = (uint32_t*)pwh;
    uint32_t* wl = (uint32_t*)pwl;

    cudaFuncSetAttribute(k_gemm<false>,
                         cudaFuncAttributeMaxDynamicSharedMemorySize, GEMM_SMEM);
    cudaFuncSetAttribute(k_gemm<true>,
                         cudaFuncAttributeMaxDynamicSharedMemorySize, GEMM_SMEM);

    const int EB = (N_EDGES + 255) / 256;
    const int GEMM_GRID = (N_NODES + 64 * SUBT - 1) / (64 * SUBT);  // 782
    const int TILE_GRID = (N_NODES + 63) / 64;                      // 1563
    const int AGG_BLOCKS = (N_NODES * 32 + 255) / 256;              // 12500

    // ---- preprocessing ----
    k_deg<<<EB, 256>>>(edge, W1, W2);
    k_scan<<<NB, SCAN_T>>>();
    k_scatter<<<EB, 256>>>(edge);

    // ---- layer 1: t1 = X@W1 (fp16); h1 = relu(A t1 + b1) (fp16) ----
    k_gemm<false><<<GEMM_GRID, 256, GEMM_SMEM>>>(x, wh, wl, t1);
    k_agg<<<AGG_BLOCKS, 256>>>(t1, h1, b1);

    // ---- layer 2: t2 = h1@W2 (fp16); fused agg2 + pool ----
    k_gemm<true><<<GEMM_GRID, 256, GEMM_SMEM>>>(h1, wh + D * 64, wl + D * 64, t2);
    k_fused_ap<<<TILE_GRID, 256>>>(t2, b2, batch);

    // ---- fc ----
    k_fc<<<N_GRAPHS, D>>>(Wfc, bfc, out);
}

// round 9
// speedup vs baseline: 1.3585x; 1.1178x over previous
#include <cuda_runtime.h>
#include <cuda_bf16.h>
#include <cuda_fp16.h>
#include <cstdint>

#define N_NODES 100000
#define N_EDGES 1600000
#define N_GRAPHS 64
#define D 128

#define SCAN_T 1024
#define NB ((N_NODES + SCAN_T - 1) / SCAN_T)   // 98

// ---------------- scratch (device globals; no allocation allowed) ----------
__device__ __half g_t1[(size_t)N_NODES * D];  // X@W1, fp16
__device__ __half g_h1[(size_t)N_NODES * D];  // relu(A t1 + b1), fp16
__device__ __half g_t2[(size_t)N_NODES * D];  // h1@W2, fp16
__device__ int   g_deg[N_NODES];              // zeroed by k_fused_ap for next call
__device__ float g_dinv[N_NODES];
__device__ int   g_off[N_NODES + 1];
__device__ int   g_cur[N_NODES];
__device__ uint2 g_csr[N_EDGES];              // .x = src, .y = weight bits
__device__ int   g_bsum[NB];                  // re-armed to -1 by k_deg
__device__ float g_pool[N_GRAPHS * D];        // zeroed by k_gemm
__device__ int   g_cnt[N_GRAPHS];
__device__ int   g_is64;
__device__ uint32_t g_W16[2][D * 64];         // W^T fp16, packed pairs [n][k/2]

// ---------------- helpers ---------------------------------------------------
__device__ __forceinline__ int load_idx(const void* p, long long i) {
    if (g_is64) return (int)((const long long*)p)[i];
    return ((const int*)p)[i];
}

__device__ __forceinline__ int detect64(const void* ep) {
    const int* p = (const int*)ep;
    int is64 = 1;
    #pragma unroll
    for (int j = 0; j < 8; j++)
        if (p[2 * j + 1] != 0) is64 = 0;
    return is64;
}

// fp16 x fp16 -> fp32 MMA (exact products, fp32 accumulate)
__device__ __forceinline__ void mma16f(float* c, const uint32_t* a,
                                       const uint32_t* b) {
    asm volatile(
        "mma.sync.aligned.m16n8k16.row.col.f32.f16.f16.f32 "
        "{%0,%1,%2,%3}, {%4,%5,%6,%7}, {%8,%9}, {%0,%1,%2,%3};"
        : "+f"(c[0]), "+f"(c[1]), "+f"(c[2]), "+f"(c[3])
        : "r"(a[0]), "r"(a[1]), "r"(a[2]), "r"(a[3]), "r"(b[0]), "r"(b[1]));
}

__device__ __forceinline__ float4 h4tof4(uint2 v) {
    float2 a = __half22float2(*reinterpret_cast<__half2*>(&v.x));
    float2 b = __half22float2(*reinterpret_cast<__half2*>(&v.y));
    return make_float4(a.x, a.y, b.x, b.y);
}

__device__ __forceinline__ uint2 f4toh4(float4 v) {
    __half2 a = __float22half2_rn(make_float2(v.x, v.y));
    __half2 b = __float22half2_rn(make_float2(v.z, v.w));
    uint2 o;
    o.x = *reinterpret_cast<uint32_t*>(&a);
    o.y = *reinterpret_cast<uint32_t*>(&b);
    return o;
}

// gather one node row from fp16 features:
// relu( dinv^2*h[node] + sum_e w*h[src] + bias )
__device__ __forceinline__ float4 gather_row16(const uint2* __restrict__ hp,
                                               int node, int lane,
                                               const float4 b) {
    float dii = g_dinv[node];
    float sw = dii * dii;
    float4 s = h4tof4(hp[(size_t)node * 32 + lane]);
    float4 acc[4];
    acc[0] = make_float4(s.x * sw, s.y * sw, s.z * sw, s.w * sw);
    acc[1] = make_float4(0.f, 0.f, 0.f, 0.f);
    acc[2] = acc[1];
    acc[3] = acc[1];

    int e = g_off[node];
    const int end = g_off[node + 1];
    for (; e + 3 < end; e += 4) {
        uint2 p[4];
        #pragma unroll
        for (int j = 0; j < 4; j++) p[j] = g_csr[e + j];
        uint2 raw[4];
        #pragma unroll
        for (int j = 0; j < 4; j++) raw[j] = hp[(size_t)p[j].x * 32 + lane];
        #pragma unroll
        for (int j = 0; j < 4; j++) {
            float w = __uint_as_float(p[j].y);
            float4 v = h4tof4(raw[j]);
            acc[j].x = fmaf(v.x, w, acc[j].x);
            acc[j].y = fmaf(v.y, w, acc[j].y);
            acc[j].z = fmaf(v.z, w, acc[j].z);
            acc[j].w = fmaf(v.w, w, acc[j].w);
        }
    }
    for (; e < end; e++) {
        uint2 p = g_csr[e];
        float w = __uint_as_float(p.y);
        float4 v = h4tof4(hp[(size_t)p.x * 32 + lane]);
        acc[0].x = fmaf(v.x, w, acc[0].x);
        acc[0].y = fmaf(v.y, w, acc[0].y);
        acc[0].z = fmaf(v.z, w, acc[0].z);
        acc[0].w = fmaf(v.w, w, acc[0].w);
    }
    float4 r;
    r.x = fmaxf(acc[0].x + acc[1].x + acc[2].x + acc[3].x + b.x, 0.f);
    r.y = fmaxf(acc[0].y + acc[1].y + acc[2].y + acc[3].y + b.y, 0.f);
    r.z = fmaxf(acc[0].z + acc[1].z + acc[2].z + acc[3].z + b.z, 0.f);
    r.w = fmaxf(acc[0].w + acc[1].w + acc[2].w + acc[3].w + b.w, 0.f);
    return r;
}

// ---------------- deg count + init (W fp16 transpose, dtype, sentinels) -----
__global__ void k_deg(const void* ep, const float* W1, const float* W2) {
    int i = blockIdx.x * blockDim.x + threadIdx.x;
    if (i == 0) {
        g_is64 = detect64(ep);
        g_off[N_NODES] = N_EDGES;
    }
    if (i < NB) g_bsum[i] = -1;    // arm scan publication sentinel
    if (i < 2 * D * 64) {          // one packed fp16 pair of W^T per thread
        int m = i >> 13;           // 0 -> W1, 1 -> W2
        int j = i & 8191;
        int n = j >> 6, kp = j & 63;
        const float* W = m ? W2 : W1;
        float a = W[(2 * kp) * D + n];       // W^T[n][2kp]
        float b = W[(2 * kp + 1) * D + n];
        __half2 h = __float22half2_rn(make_float2(a, b));
        g_W16[m][n * 64 + kp] = *reinterpret_cast<uint32_t*>(&h);
    }
    if (i < N_EDGES) {
        int is64 = detect64(ep);
        int d = is64 ? (int)((const long long*)ep)[(long long)N_EDGES + i]
                     : ((const int*)ep)[N_EDGES + i];
        atomicAdd(&g_deg[d], 1);
    }
}

// ---------------- single-pass scan (98 blocks = 1 wave; spin publication) ---
__global__ void k_scan() {
    __shared__ int s[SCAN_T];
    __shared__ int s_boff;
    const int b = blockIdx.x;
    const int t = threadIdx.x;
    const int i = b * SCAN_T + t;
    int v = (i < N_NODES) ? g_deg[i] : 0;
    if (i < N_NODES) g_dinv[i] = rsqrtf((float)v + 1.0f);  // +1 self loop
    s[t] = v;
    if (t == 0) s_boff = 0;
    __syncthreads();
    #pragma unroll
    for (int off = 1; off < SCAN_T; off <<= 1) {
        int u = (t >= off) ? s[t - off] : 0;
        __syncthreads();
        s[t] += u;
        __syncthreads();
    }
    if (t == SCAN_T - 1)
        ((volatile int*)g_bsum)[b] = s[SCAN_T - 1];
    if (t < b) {
        int val;
        do { val = ((volatile int*)g_bsum)[t]; } while (val < 0);
        atomicAdd(&s_boff, val);
    }
    __syncthreads();
    if (i < N_NODES) {
        int off = s[t] - v + s_boff;
        g_off[i] = off;
        g_cur[i] = off;
    }
}

// ---------------- CSR scatter (counting sort by dst, packed 8B entries) -----
__global__ void k_scatter(const void* ep) {
    int e = blockIdx.x * blockDim.x + threadIdx.x;
    if (e >= N_EDGES) return;
    int s = load_idx(ep, e);
    int d = load_idx(ep, (long long)N_EDGES + e);
    int pos = atomicAdd(&g_cur[d], 1);
    float w = g_dinv[s] * g_dinv[d];
    g_csr[pos] = make_uint2((uint32_t)s, __float_as_uint(w));
}

// ---------------- GEMM: Y16 = X @ W (pure fp16 MMA, fp32 accum) -------------
// CTA: 256 thr; W staged once (fp16), SUBT 64-row A sub-tiles.
#define KS 136
#define SUBT 2
#define GEMM_SMEM ((64 * KS + 128 * KS) * 2)   // 52224 B -> 4 CTAs/SM

template <bool HALF_IN>
__global__ void __launch_bounds__(256) k_gemm(const void* __restrict__ Xv,
                                              const uint32_t* __restrict__ Wp,
                                              __half* __restrict__ Y16) {
    extern __shared__ __half sm[];
    __half* sA = sm;                 // [64][136]
    __half* sW = sA + 64 * KS;       // [128][136]

    const int tid = threadIdx.x;
    const int rowBase0 = blockIdx.x * (64 * SUBT);

    // zero pool/cnt for this call's fused_ap (idempotent)
    int gtid = blockIdx.x * 256 + tid;
    if (gtid < N_GRAPHS * D) g_pool[gtid] = 0.0f;
    if (gtid < N_GRAPHS) g_cnt[gtid] = 0;

    // ---- stage W once (fp16) ----
    const uint4* Wp4 = (const uint4*)Wp;
    uint32_t* sW32 = (uint32_t*)sW;
    #pragma unroll
    for (int i = tid; i < 128 * 16; i += 256) {
        int n = i >> 4, kq = i & 15;
        *(uint4*)&sW32[n * (KS / 2) + kq * 4] = Wp4[i];
    }

    const int wid = tid >> 5, lane = tid & 31;
    const int g = lane >> 2, tg = lane & 3;
    const int mbase = (wid >> 2) * 32;
    const int nbase = (wid & 3) * 32;

    for (int st = 0; st < SUBT; st++) {
        const int rowBase = rowBase0 + st * 64;
        if (st) __syncthreads();

        // ---- stage A sub-tile (fp16) ----
        #pragma unroll
        for (int i = tid; i < 64 * 32; i += 256) {
            int r = i >> 5, c4 = i & 31;
            uint2 hv = make_uint2(0u, 0u);
            if (rowBase + r < N_NODES) {
                if (HALF_IN)
                    hv = ((const uint2*)Xv)[(size_t)(rowBase + r) * 32 + c4];
                else
                    hv = f4toh4(((const float4*)Xv)[(size_t)(rowBase + r) * 32 + c4]);
            }
            *(uint2*)&sA[r * KS + c4 * 4] = hv;
        }
        __syncthreads();

        float acc[2][4][4];
        #pragma unroll
        for (int mf = 0; mf < 2; mf++)
            #pragma unroll
            for (int nf = 0; nf < 4; nf++)
                #pragma unroll
                for (int j = 0; j < 4; j++) acc[mf][nf][j] = 0.f;

        #pragma unroll
        for (int kc = 0; kc < 8; kc++) {
            const int kA = kc * 16 + 2 * tg;
            uint32_t a[2][4];
            #pragma unroll
            for (int mf = 0; mf < 2; mf++) {
                int r = mbase + mf * 16 + g;
                a[mf][0] = *(uint32_t*)&sA[r * KS + kA];
                a[mf][1] = *(uint32_t*)&sA[(r + 8) * KS + kA];
                a[mf][2] = *(uint32_t*)&sA[r * KS + kA + 8];
                a[mf][3] = *(uint32_t*)&sA[(r + 8) * KS + kA + 8];
            }
            uint32_t b[4][2];
            #pragma unroll
            for (int nf = 0; nf < 4; nf++) {
                int n = nbase + nf * 8 + g;
                b[nf][0] = *(uint32_t*)&sW[n * KS + kA];
                b[nf][1] = *(uint32_t*)&sW[n * KS + kA + 8];
            }
            #pragma unroll
            for (int mf = 0; mf < 2; mf++)
                #pragma unroll
                for (int nf = 0; nf < 4; nf++)
                    mma16f(acc[mf][nf], a[mf], b[nf]);
        }

        // ---- epilogue: fp16 out ----
        #pragma unroll
        for (int mf = 0; mf < 2; mf++) {
            int row = rowBase + mbase + mf * 16 + g;
            #pragma unroll
            for (int nf = 0; nf < 4; nf++) {
                int col = nbase + nf * 8 + 2 * tg;
                if (row < N_NODES) {
                    __half2 h = __float22half2_rn(
                        make_float2(acc[mf][nf][0], acc[mf][nf][1]));
                    *(__half2*)&Y16[(size_t)row * D + col] = h;
                }
                if (row + 8 < N_NODES) {
                    __half2 h = __float22half2_rn(
                        make_float2(acc[mf][nf][2], acc[mf][nf][3]));
                    *(__half2*)&Y16[(size_t)(row + 8) * D + col] = h;
                }
            }
        }
    }
}

// ---------------- agg1: h1 = relu(A t1 + b1), fp16 in/out -------------------
__global__ void k_agg(const __half* __restrict__ hin,
                      __half* __restrict__ hout,
                      const float* __restrict__ bias) {
    int node = (blockIdx.x * blockDim.x + threadIdx.x) >> 5;
    if (node >= N_NODES) return;
    int lane = threadIdx.x & 31;

    const uint2* hp = (const uint2*)hin;
    const float4 b = ((const float4*)bias)[lane];
    float4 r = gather_row16(hp, node, lane, b);
    ((uint2*)hout)[(size_t)node * 32 + lane] = f4toh4(r);
}

// ---------------- FUSED B: h2 = relu(A t2 + b2); pool atomics ---------------
#define HS 132
__global__ void __launch_bounds__(256) k_fused_ap(const __half* __restrict__ T2,
                                                  const float* __restrict__ bias,
                                                  const void* batchp) {
    __shared__ float sH[64 * HS];
    __shared__ int sg[64];

    const int tid = threadIdx.x;
    const int wid = tid >> 5, lane = tid & 31;
    const int rowBase = blockIdx.x * 64;
    const int n_here = min(64, N_NODES - rowBase);

    if (tid < 64 && rowBase + tid < N_NODES) {
        sg[tid] = load_idx(batchp, rowBase + tid);
        g_deg[rowBase + tid] = 0;            // prep next replay
    }

    const uint2* hp = (const uint2*)T2;
    const float4 bvec = ((const float4*)bias)[lane];
    #pragma unroll
    for (int i = 0; i < 8; i++) {
        int r = wid * 8 + i;
        int node = rowBase + r;
        if (node < N_NODES) {
            float4 v = gather_row16(hp, node, lane, bvec);
            *(float4*)&sH[r * HS + lane * 4] = v;
        }
    }
    __syncthreads();

    // ---- pool: run-length accumulate, rare atomics (batch sorted) ----
    if (tid < 128) {
        float acc = 0.f;
        int cur = sg[0];
        int runstart = 0;
        for (int n = 0; n < n_here; n++) {
            int g = sg[n];
            if (g != cur) {
                atomicAdd(&g_pool[cur * D + tid], acc);
                if (tid == 0) atomicAdd(&g_cnt[cur], n - runstart);
                acc = 0.f; cur = g; runstart = n;
            }
            acc += sH[n * HS + tid];
        }
        atomicAdd(&g_pool[cur * D + tid], acc);
        if (tid == 0) atomicAdd(&g_cnt[cur], n_here - runstart);
    }
}

// ---------------- final FC: out = relu( (pool/cnt) @ Wfc + bfc ) ------------
__global__ void k_fc(const float* __restrict__ Wfc,
                     const float* __restrict__ bfc,
                     float* __restrict__ out) {
    __shared__ float srow[D];
    int g = blockIdx.x;
    int t = threadIdx.x;
    float cnt = fmaxf((float)g_cnt[g], 1.0f);
    srow[t] = g_pool[g * D + t] / cnt;
    __syncthreads();
    float acc = bfc[t];
    #pragma unroll 4
    for (int k = 0; k < D; k++)
        acc = fmaf(srow[k], Wfc[k * D + t], acc);
    out[g * D + t] = fmaxf(acc, 0.f);
}

// ---------------- launch ----------------------------------------------------
extern "C" void kernel_launch(void* const* d_in, const int* in_sizes, int n_in,
                              void* d_out, int out_size) {
    const float* x    = (const float*)d_in[0];
    const void*  edge = d_in[1];
    const void*  batch= d_in[2];
    const float* W1   = (const float*)d_in[3];
    const float* b1   = (const float*)d_in[4];
    const float* W2   = (const float*)d_in[5];
    const float* b2   = (const float*)d_in[6];
    const float* Wfc  = (const float*)d_in[7];
    const float* bfc  = (const float*)d_in[8];
    float* out = (float*)d_out;

    void *pt1, *pt2, *ph1, *pw;
    cudaGetSymbolAddress(&pt1, g_t1);
    cudaGetSymbolAddress(&pt2, g_t2);
    cudaGetSymbolAddress(&ph1, g_h1);
    cudaGetSymbolAddress(&pw, g_W16);
    __half* t1 = (__half*)pt1;
    __half* t2 = (__half*)pt2;
    __half* h1 = (__half*)ph1;
    uint32_t* wp = (uint32_t*)pw;

    cudaFuncSetAttribute(k_gemm<false>,
                         cudaFuncAttributeMaxDynamicSharedMemorySize, GEMM_SMEM);
    cudaFuncSetAttribute(k_gemm<true>,
                         cudaFuncAttributeMaxDynamicSharedMemorySize, GEMM_SMEM);

    const int EB = (N_EDGES + 255) / 256;
    const int GEMM_GRID = (N_NODES + 64 * SUBT - 1) / (64 * SUBT);  // 782
    const int TILE_GRID = (N_NODES + 63) / 64;                      // 1563
    const int AGG_BLOCKS = (N_NODES * 32 + 255) / 256;              // 12500

    // ---- preprocessing ----
    k_deg<<<EB, 256>>>(edge, W1, W2);
    k_scan<<<NB, SCAN_T>>>();
    k_scatter<<<EB, 256>>>(edge);

    // ---- layer 1: t1 = X@W1 (fp16); h1 = relu(A t1 + b1) (fp16) ----
    k_gemm<false><<<GEMM_GRID, 256, GEMM_SMEM>>>(x, wp, t1);
    k_agg<<<AGG_BLOCKS, 256>>>(t1, h1, b1);

    // ---- layer 2: t2 = h1@W2 (fp16); fused agg2 + pool ----
    k_gemm<true><<<GEMM_GRID, 256, GEMM_SMEM>>>(h1, wp + D * 64, t2);
    k_fused_ap<<<TILE_GRID, 256>>>(t2, b2, batch);

    // ---- fc ----
    k_fc<<<N_GRAPHS, D>>>(Wfc, bfc, out);
}

// round 10
// speedup vs baseline: 1.3620x; 1.0026x over previous
#include <cuda_runtime.h>
#include <cuda_bf16.h>
#include <cuda_fp16.h>
#include <cstdint>

#define N_NODES 100000
#define N_EDGES 1600000
#define N_GRAPHS 64
#define D 128

#define SCAN_T 1024
#define NB ((N_NODES + SCAN_T - 1) / SCAN_T)   // 98

// ---------------- scratch (device globals; no allocation allowed) ----------
__device__ __half g_t1[(size_t)N_NODES * D];  // X@W1, fp16
__device__ __half g_h1[(size_t)N_NODES * D];  // relu(A t1 + b1), fp16
__device__ __half g_t2[(size_t)N_NODES * D];  // h1@W2, fp16
__device__ int   g_deg[N_NODES];              // zeroed by k_fused_ap for next call
__device__ float g_dinv[N_NODES];
__device__ int   g_off[N_NODES + 1];
__device__ int   g_cur[N_NODES];
__device__ uint2 g_csr[N_EDGES];              // .x = src, .y = weight bits
__device__ int   g_bsum[NB];                  // re-armed to -1 by k_deg
__device__ float g_pool[N_GRAPHS * D];        // zeroed by k_gemm
__device__ int   g_cnt[N_GRAPHS];
__device__ int   g_is64;
__device__ uint32_t g_W16[2][D * 64];         // W^T fp16, packed pairs [n][k/2]

// ---------------- helpers ---------------------------------------------------
__device__ __forceinline__ int load_idx(const void* p, long long i) {
    if (g_is64) return (int)((const long long*)p)[i];
    return ((const int*)p)[i];
}

__device__ __forceinline__ int detect64(const void* ep) {
    const int* p = (const int*)ep;
    int is64 = 1;
    #pragma unroll
    for (int j = 0; j < 8; j++)
        if (p[2 * j + 1] != 0) is64 = 0;
    return is64;
}

// fp16 x fp16 -> fp32 MMA (exact products, fp32 accumulate)
__device__ __forceinline__ void mma16f(float* c, const uint32_t* a,
                                       const uint32_t* b) {
    asm volatile(
        "mma.sync.aligned.m16n8k16.row.col.f32.f16.f16.f32 "
        "{%0,%1,%2,%3}, {%4,%5,%6,%7}, {%8,%9}, {%0,%1,%2,%3};"
        : "+f"(c[0]), "+f"(c[1]), "+f"(c[2]), "+f"(c[3])
        : "r"(a[0]), "r"(a[1]), "r"(a[2]), "r"(a[3]), "r"(b[0]), "r"(b[1]));
}

__device__ __forceinline__ void ldsm_x4(uint32_t& r0, uint32_t& r1,
                                        uint32_t& r2, uint32_t& r3,
                                        uint32_t addr) {
    asm volatile(
        "ldmatrix.sync.aligned.m8n8.x4.shared.b16 {%0,%1,%2,%3}, [%4];"
        : "=r"(r0), "=r"(r1), "=r"(r2), "=r"(r3) : "r"(addr));
}

__device__ __forceinline__ uint32_t sptr(const void* p) {
    return (uint32_t)__cvta_generic_to_shared(p);
}

__device__ __forceinline__ float4 h4tof4(uint2 v) {
    float2 a = __half22float2(*reinterpret_cast<__half2*>(&v.x));
    float2 b = __half22float2(*reinterpret_cast<__half2*>(&v.y));
    return make_float4(a.x, a.y, b.x, b.y);
}

__device__ __forceinline__ uint2 f4toh4(float4 v) {
    __half2 a = __float22half2_rn(make_float2(v.x, v.y));
    __half2 b = __float22half2_rn(make_float2(v.z, v.w));
    uint2 o;
    o.x = *reinterpret_cast<uint32_t*>(&a);
    o.y = *reinterpret_cast<uint32_t*>(&b);
    return o;
}

// gather one node row from fp16 features:
// relu( dinv^2*h[node] + sum_e w*h[src] + bias )
__device__ __forceinline__ float4 gather_row16(const uint2* __restrict__ hp,
                                               int node, int lane,
                                               const float4 b) {
    float dii = g_dinv[node];
    float sw = dii * dii;
    float4 s = h4tof4(hp[(size_t)node * 32 + lane]);
    float4 acc[4];
    acc[0] = make_float4(s.x * sw, s.y * sw, s.z * sw, s.w * sw);
    acc[1] = make_float4(0.f, 0.f, 0.f, 0.f);
    acc[2] = acc[1];
    acc[3] = acc[1];

    int e = g_off[node];
    const int end = g_off[node + 1];
    for (; e + 3 < end; e += 4) {
        uint2 p[4];
        #pragma unroll
        for (int j = 0; j < 4; j++) p[j] = g_csr[e + j];
        uint2 raw[4];
        #pragma unroll
        for (int j = 0; j < 4; j++) raw[j] = hp[(size_t)p[j].x * 32 + lane];
        #pragma unroll
        for (int j = 0; j < 4; j++) {
            float w = __uint_as_float(p[j].y);
            float4 v = h4tof4(raw[j]);
            acc[j].x = fmaf(v.x, w, acc[j].x);
            acc[j].y = fmaf(v.y, w, acc[j].y);
            acc[j].z = fmaf(v.z, w, acc[j].z);
            acc[j].w = fmaf(v.w, w, acc[j].w);
        }
    }
    for (; e < end; e++) {
        uint2 p = g_csr[e];
        float w = __uint_as_float(p.y);
        float4 v = h4tof4(hp[(size_t)p.x * 32 + lane]);
        acc[0].x = fmaf(v.x, w, acc[0].x);
        acc[0].y = fmaf(v.y, w, acc[0].y);
        acc[0].z = fmaf(v.z, w, acc[0].z);
        acc[0].w = fmaf(v.w, w, acc[0].w);
    }
    float4 r;
    r.x = fmaxf(acc[0].x + acc[1].x + acc[2].x + acc[3].x + b.x, 0.f);
    r.y = fmaxf(acc[0].y + acc[1].y + acc[2].y + acc[3].y + b.y, 0.f);
    r.z = fmaxf(acc[0].z + acc[1].z + acc[2].z + acc[3].z + b.z, 0.f);
    r.w = fmaxf(acc[0].w + acc[1].w + acc[2].w + acc[3].w + b.w, 0.f);
    return r;
}

// ---------------- deg count + init (W fp16 transpose, dtype, sentinels) -----
__global__ void k_deg(const void* ep, const float* W1, const float* W2) {
    int i = blockIdx.x * blockDim.x + threadIdx.x;
    if (i == 0) {
        g_is64 = detect64(ep);
        g_off[N_NODES] = N_EDGES;
    }
    if (i < NB) g_bsum[i] = -1;    // arm scan publication sentinel
    if (i < 2 * D * 64) {          // one packed fp16 pair of W^T per thread
        int m = i >> 13;           // 0 -> W1, 1 -> W2
        int j = i & 8191;
        int n = j >> 6, kp = j & 63;
        const float* W = m ? W2 : W1;
        float a = W[(2 * kp) * D + n];       // W^T[n][2kp]
        float b = W[(2 * kp + 1) * D + n];
        __half2 h = __float22half2_rn(make_float2(a, b));
        g_W16[m][n * 64 + kp] = *reinterpret_cast<uint32_t*>(&h);
    }
    if (i < N_EDGES) {
        int is64 = detect64(ep);
        int d = is64 ? (int)((const long long*)ep)[(long long)N_EDGES + i]
                     : ((const int*)ep)[N_EDGES + i];
        atomicAdd(&g_deg[d], 1);
    }
}

// ---------------- single-pass scan (98 blocks = 1 wave; spin publication) ---
__global__ void k_scan() {
    __shared__ int s[SCAN_T];
    __shared__ int s_boff;
    const int b = blockIdx.x;
    const int t = threadIdx.x;
    const int i = b * SCAN_T + t;
    int v = (i < N_NODES) ? g_deg[i] : 0;
    if (i < N_NODES) g_dinv[i] = rsqrtf((float)v + 1.0f);  // +1 self loop
    s[t] = v;
    if (t == 0) s_boff = 0;
    __syncthreads();
    #pragma unroll
    for (int off = 1; off < SCAN_T; off <<= 1) {
        int u = (t >= off) ? s[t - off] : 0;
        __syncthreads();
        s[t] += u;
        __syncthreads();
    }
    if (t == SCAN_T - 1)
        ((volatile int*)g_bsum)[b] = s[SCAN_T - 1];
    if (t < b) {
        int val;
        do { val = ((volatile int*)g_bsum)[t]; } while (val < 0);
        atomicAdd(&s_boff, val);
    }
    __syncthreads();
    if (i < N_NODES) {
        int off = s[t] - v + s_boff;
        g_off[i] = off;
        g_cur[i] = off;
    }
}

// ---------------- CSR scatter (counting sort by dst, packed 8B entries) -----
__global__ void k_scatter(const void* ep) {
    int e = blockIdx.x * blockDim.x + threadIdx.x;
    if (e >= N_EDGES) return;
    int s = load_idx(ep, e);
    int d = load_idx(ep, (long long)N_EDGES + e);
    int pos = atomicAdd(&g_cur[d], 1);
    float w = g_dinv[s] * g_dinv[d];
    g_csr[pos] = make_uint2((uint32_t)s, __float_as_uint(w));
}

// ---------------- GEMM: Y16 = X @ W (pure fp16 MMA, ldmatrix frags) ---------
// CTA: 256 thr; W staged once (fp16), SUBT 64-row A sub-tiles; grid = 1 wave.
#define KS 136
#define SUBT 4
#define GEMM_SMEM ((64 * KS + 128 * KS) * 2)   // 52224 B -> 4 CTAs/SM

template <bool HALF_IN>
__global__ void __launch_bounds__(256) k_gemm(const void* __restrict__ Xv,
                                              const uint32_t* __restrict__ Wp,
                                              __half* __restrict__ Y16) {
    extern __shared__ __half sm[];
    __half* sA = sm;                 // [64][136]
    __half* sW = sA + 64 * KS;       // [128][136]

    const int tid = threadIdx.x;
    const int rowBase0 = blockIdx.x * (64 * SUBT);

    // zero pool/cnt for this call's fused_ap (idempotent)
    int gtid = blockIdx.x * 256 + tid;
    if (gtid < N_GRAPHS * D) g_pool[gtid] = 0.0f;
    if (gtid < N_GRAPHS) g_cnt[gtid] = 0;

    // ---- stage W once (fp16) ----
    const uint4* Wp4 = (const uint4*)Wp;
    uint32_t* sW32 = (uint32_t*)sW;
    #pragma unroll
    for (int i = tid; i < 128 * 16; i += 256) {
        int n = i >> 4, kq = i & 15;
        *(uint4*)&sW32[n * (KS / 2) + kq * 4] = Wp4[i];
    }

    const int wid = tid >> 5, lane = tid & 31;
    const int g = lane >> 2, tg = lane & 3;
    const int mbase = (wid >> 2) * 32;
    const int nbase = (wid & 3) * 32;

    // ldmatrix lane addressing: j = lane>>3 selects the 8x8 sub-matrix
    const int jj = lane >> 3, rr = lane & 7;
    // A x4: m0=(rows 0-7,k0-7) m1=(rows 8-15,k0-7) m2=(rows 0-7,k8-15) m3=(rows 8-15,k8-15)
    uint32_t aBase[2];
    #pragma unroll
    for (int mf = 0; mf < 2; mf++) {
        int row = mbase + mf * 16 + ((jj & 1) * 8) + rr;
        int col = (jj >> 1) * 8;
        aBase[mf] = sptr(&sA[row * KS + col]);
    }
    // B x4 (two nf per call): m0=(nf0,k0) m1=(nf0,k8) m2=(nf1,k0) m3=(nf1,k8)
    uint32_t bBase[2];
    #pragma unroll
    for (int p = 0; p < 2; p++) {
        int row = nbase + p * 16 + ((jj >> 1) * 8) + rr;
        int col = (jj & 1) * 8;
        bBase[p] = sptr(&sW[row * KS + col]);
    }

    for (int st = 0; st < SUBT; st++) {
        const int rowBase = rowBase0 + st * 64;
        if (st) __syncthreads();

        // ---- stage A sub-tile (fp16) ----
        #pragma unroll
        for (int i = tid; i < 64 * 32; i += 256) {
            int r = i >> 5, c4 = i & 31;
            uint2 hv = make_uint2(0u, 0u);
            if (rowBase + r < N_NODES) {
                if (HALF_IN)
                    hv = ((const uint2*)Xv)[(size_t)(rowBase + r) * 32 + c4];
                else
                    hv = f4toh4(((const float4*)Xv)[(size_t)(rowBase + r) * 32 + c4]);
            }
            *(uint2*)&sA[r * KS + c4 * 4] = hv;
        }
        __syncthreads();

        float acc[2][4][4];
        #pragma unroll
        for (int mf = 0; mf < 2; mf++)
            #pragma unroll
            for (int nf = 0; nf < 4; nf++)
                #pragma unroll
                for (int j = 0; j < 4; j++) acc[mf][nf][j] = 0.f;

        #pragma unroll
        for (int kc = 0; kc < 8; kc++) {
            const uint32_t koff = kc * 32;   // 16 halfs = 32 bytes
            uint32_t a[2][4];
            #pragma unroll
            for (int mf = 0; mf < 2; mf++)
                ldsm_x4(a[mf][0], a[mf][1], a[mf][2], a[mf][3],
                        aBase[mf] + koff);
            uint32_t b[4][2];
            #pragma unroll
            for (int p = 0; p < 2; p++)
                ldsm_x4(b[2 * p][0], b[2 * p][1], b[2 * p + 1][0],
                        b[2 * p + 1][1], bBase[p] + koff);
            #pragma unroll
            for (int mf = 0; mf < 2; mf++)
                #pragma unroll
                for (int nf = 0; nf < 4; nf++)
                    mma16f(acc[mf][nf], a[mf], b[nf]);
        }

        // ---- epilogue: fp16 out ----
        #pragma unroll
        for (int mf = 0; mf < 2; mf++) {
            int row = rowBase + mbase + mf * 16 + g;
            #pragma unroll
            for (int nf = 0; nf < 4; nf++) {
                int col = nbase + nf * 8 + 2 * tg;
                if (row < N_NODES) {
                    __half2 h = __float22half2_rn(
                        make_float2(acc[mf][nf][0], acc[mf][nf][1]));
                    *(__half2*)&Y16[(size_t)row * D + col] = h;
                }
                if (row + 8 < N_NODES) {
                    __half2 h = __float22half2_rn(
                        make_float2(acc[mf][nf][2], acc[mf][nf][3]));
                    *(__half2*)&Y16[(size_t)(row + 8) * D + col] = h;
                }
            }
        }
    }
}

// ---------------- agg1: h1 = relu(A t1 + b1), fp16 in/out -------------------
__global__ void k_agg(const __half* __restrict__ hin,
                      __half* __restrict__ hout,
                      const float* __restrict__ bias) {
    int node = (blockIdx.x * blockDim.x + threadIdx.x) >> 5;
    if (node >= N_NODES) return;
    int lane = threadIdx.x & 31;

    const uint2* hp = (const uint2*)hin;
    const float4 b = ((const float4*)bias)[lane];
    float4 r = gather_row16(hp, node, lane, b);
    ((uint2*)hout)[(size_t)node * 32 + lane] = f4toh4(r);
}

// ---------------- FUSED B: h2 = relu(A t2 + b2); pool atomics ---------------
#define HS 132
__global__ void __launch_bounds__(256) k_fused_ap(const __half* __restrict__ T2,
                                                  const float* __restrict__ bias,
                                                  const void* batchp) {
    __shared__ float sH[64 * HS];
    __shared__ int sg[64];

    const int tid = threadIdx.x;
    const int wid = tid >> 5, lane = tid & 31;
    const int rowBase = blockIdx.x * 64;
    const int n_here = min(64, N_NODES - rowBase);

    if (tid < 64 && rowBase + tid < N_NODES) {
        sg[tid] = load_idx(batchp, rowBase + tid);
        g_deg[rowBase + tid] = 0;            // prep next replay
    }

    const uint2* hp = (const uint2*)T2;
    const float4 bvec = ((const float4*)bias)[lane];
    #pragma unroll
    for (int i = 0; i < 8; i++) {
        int r = wid * 8 + i;
        int node = rowBase + r;
        if (node < N_NODES) {
            float4 v = gather_row16(hp, node, lane, bvec);
            *(float4*)&sH[r * HS + lane * 4] = v;
        }
    }
    __syncthreads();

    // ---- pool: run-length accumulate, rare atomics (batch sorted) ----
    if (tid < 128) {
        float acc = 0.f;
        int cur = sg[0];
        int runstart = 0;
        for (int n = 0; n < n_here; n++) {
            int g = sg[n];
            if (g != cur) {
                atomicAdd(&g_pool[cur * D + tid], acc);
                if (tid == 0) atomicAdd(&g_cnt[cur], n - runstart);
                acc = 0.f; cur = g; runstart = n;
            }
            acc += sH[n * HS + tid];
        }
        atomicAdd(&g_pool[cur * D + tid], acc);
        if (tid == 0) atomicAdd(&g_cnt[cur], n_here - runstart);
    }
}

// ---------------- final FC: out = relu( (pool/cnt) @ Wfc + bfc ) ------------
__global__ void k_fc(const float* __restrict__ Wfc,
                     const float* __restrict__ bfc,
                     float* __restrict__ out) {
    __shared__ float srow[D];
    int g = blockIdx.x;
    int t = threadIdx.x;
    float cnt = fmaxf((float)g_cnt[g], 1.0f);
    srow[t] = g_pool[g * D + t] / cnt;
    __syncthreads();
    float acc = bfc[t];
    #pragma unroll 4
    for (int k = 0; k < D; k++)
        acc = fmaf(srow[k], Wfc[k * D + t], acc);
    out[g * D + t] = fmaxf(acc, 0.f);
}

// ---------------- launch ----------------------------------------------------
extern "C" void kernel_launch(void* const* d_in, const int* in_sizes, int n_in,
                              void* d_out, int out_size) {
    const float* x    = (const float*)d_in[0];
    const void*  edge = d_in[1];
    const void*  batch= d_in[2];
    const float* W1   = (const float*)d_in[3];
    const float* b1   = (const float*)d_in[4];
    const float* W2   = (const float*)d_in[5];
    const float* b2   = (const float*)d_in[6];
    const float* Wfc  = (const float*)d_in[7];
    const float* bfc  = (const float*)d_in[8];
    float* out = (float*)d_out;

    void *pt1, *pt2, *ph1, *pw;
    cudaGetSymbolAddress(&pt1, g_t1);
    cudaGetSymbolAddress(&pt2, g_t2);
    cudaGetSymbolAddress(&ph1, g_h1);
    cudaGetSymbolAddress(&pw, g_W16);
    __half* t1 = (__half*)pt1;
    __half* t2 = (__half*)pt2;
    __half* h1 = (__half*)ph1;
    uint32_t* wp = (uint32_t*)pw;

    cudaFuncSetAttribute(k_gemm<false>,
                         cudaFuncAttributeMaxDynamicSharedMemorySize, GEMM_SMEM);
    cudaFuncSetAttribute(k_gemm<true>,
                         cudaFuncAttributeMaxDynamicSharedMemorySize, GEMM_SMEM);

    const int EB = (N_EDGES + 255) / 256;
    const int GEMM_GRID = (N_NODES + 64 * SUBT - 1) / (64 * SUBT);  // 391
    const int TILE_GRID = (N_NODES + 63) / 64;                      // 1563
    const int AGG_BLOCKS = (N_NODES * 32 + 255) / 256;              // 12500

    // ---- preprocessing ----
    k_deg<<<EB, 256>>>(edge, W1, W2);
    k_scan<<<NB, SCAN_T>>>();
    k_scatter<<<EB, 256>>>(edge);

    // ---- layer 1: t1 = X@W1 (fp16); h1 = relu(A t1 + b1) (fp16) ----
    k_gemm<false><<<GEMM_GRID, 256, GEMM_SMEM>>>(x, wp, t1);
    k_agg<<<AGG_BLOCKS, 256>>>(t1, h1, b1);

    // ---- layer 2: t2 = h1@W2 (fp16); fused agg2 + pool ----
    k_gemm<true><<<GEMM_GRID, 256, GEMM_SMEM>>>(h1, wp + D * 64, t2);
    k_fused_ap<<<TILE_GRID, 256>>>(t2, b2, batch);

    // ---- fc ----
    k_fc<<<N_GRAPHS, D>>>(Wfc, bfc, out);
}

// round 11
// speedup vs baseline: 1.3925x; 1.0224x over previous
#include <cuda_runtime.h>
#include <cuda_bf16.h>
#include <cuda_fp16.h>
#include <cstdint>

#define N_NODES 100000
#define N_EDGES 1600000
#define N_GRAPHS 64
#define D 128

#define SCAN_T 1024
#define NB ((N_NODES + SCAN_T - 1) / SCAN_T)   // 98

// ---------------- scratch (device globals; no allocation allowed) ----------
__device__ uint2  g_x16[(size_t)N_NODES * 32]; // X in fp16 (packed 4/uint2)
__device__ __half g_t1[(size_t)N_NODES * D];  // X@W1, fp16
__device__ __half g_h1[(size_t)N_NODES * D];  // relu(A t1 + b1), fp16
__device__ __half g_t2[(size_t)N_NODES * D];  // h1@W2, fp16
__device__ int   g_deg[N_NODES];              // zeroed by k_fused_ap for next call
__device__ float g_dinv[N_NODES];
__device__ int   g_off[N_NODES + 1];
__device__ int   g_cur[N_NODES];
__device__ uint2 g_csr[N_EDGES];              // .x = src, .y = weight bits
__device__ int   g_bsum[NB];                  // re-armed to -1 by k_deg
__device__ float g_pool[N_GRAPHS * D];        // zeroed by k_gemm
__device__ int   g_cnt[N_GRAPHS];
__device__ int   g_is64;
__device__ uint32_t g_W16[2][D * 64];         // W^T fp16, packed pairs [n][k/2]

// ---------------- helpers ---------------------------------------------------
__device__ __forceinline__ int load_idx(const void* p, long long i) {
    if (g_is64) return (int)((const long long*)p)[i];
    return ((const int*)p)[i];
}

__device__ __forceinline__ int detect64(const void* ep) {
    const int* p = (const int*)ep;
    int is64 = 1;
    #pragma unroll
    for (int j = 0; j < 8; j++)
        if (p[2 * j + 1] != 0) is64 = 0;
    return is64;
}

// fp16 x fp16 -> fp32 MMA (exact products, fp32 accumulate)
__device__ __forceinline__ void mma16f(float* c, const uint32_t* a,
                                       const uint32_t* b) {
    asm volatile(
        "mma.sync.aligned.m16n8k16.row.col.f32.f16.f16.f32 "
        "{%0,%1,%2,%3}, {%4,%5,%6,%7}, {%8,%9}, {%0,%1,%2,%3};"
        : "+f"(c[0]), "+f"(c[1]), "+f"(c[2]), "+f"(c[3])
        : "r"(a[0]), "r"(a[1]), "r"(a[2]), "r"(a[3]), "r"(b[0]), "r"(b[1]));
}

__device__ __forceinline__ void ldsm_x4(uint32_t& r0, uint32_t& r1,
                                        uint32_t& r2, uint32_t& r3,
                                        uint32_t addr) {
    asm volatile(
        "ldmatrix.sync.aligned.m8n8.x4.shared.b16 {%0,%1,%2,%3}, [%4];"
        : "=r"(r0), "=r"(r1), "=r"(r2), "=r"(r3) : "r"(addr));
}

__device__ __forceinline__ uint32_t sptr(const void* p) {
    return (uint32_t)__cvta_generic_to_shared(p);
}

__device__ __forceinline__ float4 h4tof4(uint2 v) {
    float2 a = __half22float2(*reinterpret_cast<__half2*>(&v.x));
    float2 b = __half22float2(*reinterpret_cast<__half2*>(&v.y));
    return make_float4(a.x, a.y, b.x, b.y);
}

__device__ __forceinline__ uint2 f4toh4(float4 v) {
    __half2 a = __float22half2_rn(make_float2(v.x, v.y));
    __half2 b = __float22half2_rn(make_float2(v.z, v.w));
    uint2 o;
    o.x = *reinterpret_cast<uint32_t*>(&a);
    o.y = *reinterpret_cast<uint32_t*>(&b);
    return o;
}

// gather one node row from fp16 features:
// relu( dinv^2*h[node] + sum_e w*h[src] + bias )
__device__ __forceinline__ float4 gather_row16(const uint2* __restrict__ hp,
                                               int node, int lane,
                                               const float4 b) {
    float dii = g_dinv[node];
    float sw = dii * dii;
    float4 s = h4tof4(hp[(size_t)node * 32 + lane]);
    float4 acc[4];
    acc[0] = make_float4(s.x * sw, s.y * sw, s.z * sw, s.w * sw);
    acc[1] = make_float4(0.f, 0.f, 0.f, 0.f);
    acc[2] = acc[1];
    acc[3] = acc[1];

    int e = g_off[node];
    const int end = g_off[node + 1];
    for (; e + 3 < end; e += 4) {
        uint2 p[4];
        #pragma unroll
        for (int j = 0; j < 4; j++) p[j] = g_csr[e + j];
        uint2 raw[4];
        #pragma unroll
        for (int j = 0; j < 4; j++) raw[j] = hp[(size_t)p[j].x * 32 + lane];
        #pragma unroll
        for (int j = 0; j < 4; j++) {
            float w = __uint_as_float(p[j].y);
            float4 v = h4tof4(raw[j]);
            acc[j].x = fmaf(v.x, w, acc[j].x);
            acc[j].y = fmaf(v.y, w, acc[j].y);
            acc[j].z = fmaf(v.z, w, acc[j].z);
            acc[j].w = fmaf(v.w, w, acc[j].w);
        }
    }
    for (; e < end; e++) {
        uint2 p = g_csr[e];
        float w = __uint_as_float(p.y);
        float4 v = h4tof4(hp[(size_t)p.x * 32 + lane]);
        acc[0].x = fmaf(v.x, w, acc[0].x);
        acc[0].y = fmaf(v.y, w, acc[0].y);
        acc[0].z = fmaf(v.z, w, acc[0].z);
        acc[0].w = fmaf(v.w, w, acc[0].w);
    }
    float4 r;
    r.x = fmaxf(acc[0].x + acc[1].x + acc[2].x + acc[3].x + b.x, 0.f);
    r.y = fmaxf(acc[0].y + acc[1].y + acc[2].y + acc[3].y + b.y, 0.f);
    r.z = fmaxf(acc[0].z + acc[1].z + acc[2].z + acc[3].z + b.z, 0.f);
    r.w = fmaxf(acc[0].w + acc[1].w + acc[2].w + acc[3].w + b.w, 0.f);
    return r;
}

// ---------------- deg count + init (W fp16, X fp16, dtype, sentinels) -------
__global__ void k_deg(const void* ep, const float* X,
                      const float* W1, const float* W2) {
    int i = blockIdx.x * blockDim.x + threadIdx.x;
    if (i == 0) {
        g_is64 = detect64(ep);
        g_off[N_NODES] = N_EDGES;
    }
    if (i < NB) g_bsum[i] = -1;    // arm scan publication sentinel
    if (i < 2 * D * 64) {          // one packed fp16 pair of W^T per thread
        int m = i >> 13;           // 0 -> W1, 1 -> W2
        int j = i & 8191;
        int n = j >> 6, kp = j & 63;
        const float* W = m ? W2 : W1;
        float a = W[(2 * kp) * D + n];       // W^T[n][2kp]
        float b = W[(2 * kp + 1) * D + n];
        __half2 h = __float22half2_rn(make_float2(a, b));
        g_W16[m][n * 64 + kp] = *reinterpret_cast<uint32_t*>(&h);
    }
    // convert X to fp16 (2 uint2 per thread; 1.6M threads cover 3.2M exactly)
    #pragma unroll
    for (int j = 0; j < 2; j++) {
        int idx = i + j * (N_NODES * 16);   // 1,600,000 stride
        if (idx < N_NODES * 32)
            g_x16[idx] = f4toh4(((const float4*)X)[idx]);
    }
    if (i < N_EDGES) {
        int is64 = detect64(ep);
        int d = is64 ? (int)((const long long*)ep)[(long long)N_EDGES + i]
                     : ((const int*)ep)[N_EDGES + i];
        atomicAdd(&g_deg[d], 1);
    }
}

// ---------------- single-pass scan (98 blocks = 1 wave; spin publication) ---
__global__ void k_scan() {
    __shared__ int s[SCAN_T];
    __shared__ int s_boff;
    const int b = blockIdx.x;
    const int t = threadIdx.x;
    const int i = b * SCAN_T + t;
    int v = (i < N_NODES) ? g_deg[i] : 0;
    if (i < N_NODES) g_dinv[i] = rsqrtf((float)v + 1.0f);  // +1 self loop
    s[t] = v;
    if (t == 0) s_boff = 0;
    __syncthreads();
    #pragma unroll
    for (int off = 1; off < SCAN_T; off <<= 1) {
        int u = (t >= off) ? s[t - off] : 0;
        __syncthreads();
        s[t] += u;
        __syncthreads();
    }
    if (t == SCAN_T - 1)
        ((volatile int*)g_bsum)[b] = s[SCAN_T - 1];
    if (t < b) {
        int val;
        do { val = ((volatile int*)g_bsum)[t]; } while (val < 0);
        atomicAdd(&s_boff, val);
    }
    __syncthreads();
    if (i < N_NODES) {
        int off = s[t] - v + s_boff;
        g_off[i] = off;
        g_cur[i] = off;
    }
}

// ---------------- CSR scatter (counting sort by dst, packed 8B entries) -----
__global__ void k_scatter(const void* ep) {
    int e = blockIdx.x * blockDim.x + threadIdx.x;
    if (e >= N_EDGES) return;
    int s = load_idx(ep, e);
    int d = load_idx(ep, (long long)N_EDGES + e);
    int pos = atomicAdd(&g_cur[d], 1);
    float w = g_dinv[s] * g_dinv[d];
    g_csr[pos] = make_uint2((uint32_t)s, __float_as_uint(w));
}

// ---------------- GEMM: Y16 = X16 @ W (fp16 MMA, pipelined A staging) -------
// CTA: 256 thr; W staged once; double-buffered A + register prefetch.
#define KS 136
#define SUBT 4
#define ABUF (64 * KS)                         // halfs per A buffer
#define GEMM_SMEM ((2 * ABUF + 128 * KS) * 2)  // 69632 B -> 3 CTAs/SM

__global__ void __launch_bounds__(256) k_gemm(const uint2* __restrict__ X16,
                                              const uint32_t* __restrict__ Wp,
                                              __half* __restrict__ Y16) {
    extern __shared__ __half sm[];
    __half* sA = sm;                 // 2 x [64][136]
    __half* sW = sA + 2 * ABUF;      // [128][136]

    const int tid = threadIdx.x;
    const int rowBase0 = blockIdx.x * (64 * SUBT);

    // zero pool/cnt for this call's fused_ap (idempotent)
    int gtid = blockIdx.x * 256 + tid;
    if (gtid < N_GRAPHS * D) g_pool[gtid] = 0.0f;
    if (gtid < N_GRAPHS) g_cnt[gtid] = 0;

    // ---- stage W once (fp16) ----
    const uint4* Wp4 = (const uint4*)Wp;
    uint32_t* sW32 = (uint32_t*)sW;
    #pragma unroll
    for (int i = tid; i < 128 * 16; i += 256) {
        int n = i >> 4, kq = i & 15;
        *(uint4*)&sW32[n * (KS / 2) + kq * 4] = Wp4[i];
    }

    const int wid = tid >> 5, lane = tid & 31;
    const int g = lane >> 2, tg = lane & 3;
    const int mbase = (wid >> 2) * 32;
    const int nbase = (wid & 3) * 32;

    // ldmatrix lane addressing
    const int jj = lane >> 3, rr = lane & 7;
    uint32_t aBase[2];            // relative to sA buffer 0
    #pragma unroll
    for (int mf = 0; mf < 2; mf++) {
        int row = mbase + mf * 16 + ((jj & 1) * 8) + rr;
        int col = (jj >> 1) * 8;
        aBase[mf] = sptr(&sA[row * KS + col]);
    }
    uint32_t bBase[2];
    #pragma unroll
    for (int p = 0; p < 2; p++) {
        int row = nbase + p * 16 + ((jj >> 1) * 8) + rr;
        int col = (jj & 1) * 8;
        bBase[p] = sptr(&sW[row * KS + col]);
    }

    // staging index for this thread (8 uint2 per thread)
    int sr[8], sc[8];
    #pragma unroll
    for (int j = 0; j < 8; j++) {
        int i = tid + j * 256;
        sr[j] = i >> 5;
        sc[j] = i & 31;
    }

    // ---- prologue: stage sub-tile 0 into buffer 0 ----
    #pragma unroll
    for (int j = 0; j < 8; j++) {
        int row = rowBase0 + sr[j];
        uint2 hv = make_uint2(0u, 0u);
        if (row < N_NODES) hv = X16[(size_t)row * 32 + sc[j]];
        *(uint2*)&sA[sr[j] * KS + sc[j] * 4] = hv;
    }
    __syncthreads();

    for (int st = 0; st < SUBT; st++) {
        const int rowBase = rowBase0 + st * 64;
        const uint32_t abytes = (uint32_t)((st & 1) * ABUF * 2);

        // ---- issue prefetch loads for st+1 (latency hidden under MMA) ----
        uint2 pref[8];
        if (st + 1 < SUBT) {
            #pragma unroll
            for (int j = 0; j < 8; j++) {
                int row = rowBase + 64 + sr[j];
                pref[j] = (row < N_NODES) ? X16[(size_t)row * 32 + sc[j]]
                                          : make_uint2(0u, 0u);
            }
        }

        // ---- MMA on buffer st&1 ----
        float acc[2][4][4];
        #pragma unroll
        for (int mf = 0; mf < 2; mf++)
            #pragma unroll
            for (int nf = 0; nf < 4; nf++)
                #pragma unroll
                for (int j = 0; j < 4; j++) acc[mf][nf][j] = 0.f;

        #pragma unroll
        for (int kc = 0; kc < 8; kc++) {
            const uint32_t koff = kc * 32;
            uint32_t a[2][4];
            #pragma unroll
            for (int mf = 0; mf < 2; mf++)
                ldsm_x4(a[mf][0], a[mf][1], a[mf][2], a[mf][3],
                        aBase[mf] + abytes + koff);
            uint32_t b[4][2];
            #pragma unroll
            for (int p = 0; p < 2; p++)
                ldsm_x4(b[2 * p][0], b[2 * p][1], b[2 * p + 1][0],
                        b[2 * p + 1][1], bBase[p] + koff);
            #pragma unroll
            for (int mf = 0; mf < 2; mf++)
                #pragma unroll
                for (int nf = 0; nf < 4; nf++)
                    mma16f(acc[mf][nf], a[mf], b[nf]);
        }

        // ---- epilogue: fp16 out ----
        #pragma unroll
        for (int mf = 0; mf < 2; mf++) {
            int row = rowBase + mbase + mf * 16 + g;
            #pragma unroll
            for (int nf = 0; nf < 4; nf++) {
                int col = nbase + nf * 8 + 2 * tg;
                if (row < N_NODES) {
                    __half2 h = __float22half2_rn(
                        make_float2(acc[mf][nf][0], acc[mf][nf][1]));
                    *(__half2*)&Y16[(size_t)row * D + col] = h;
                }
                if (row + 8 < N_NODES) {
                    __half2 h = __float22half2_rn(
                        make_float2(acc[mf][nf][2], acc[mf][nf][3]));
                    *(__half2*)&Y16[(size_t)(row + 8) * D + col] = h;
                }
            }
        }

        // ---- commit prefetch into the other buffer ----
        if (st + 1 < SUBT) {
            __syncthreads();   // all warps done reading buf (st+1)&1 (iter st-1)
            __half* dst = sA + ((st + 1) & 1) * ABUF;
            #pragma unroll
            for (int j = 0; j < 8; j++)
                *(uint2*)&dst[sr[j] * KS + sc[j] * 4] = pref[j];
            __syncthreads();   // writes visible before next MMA
        }
    }
}

// ---------------- agg1: h1 = relu(A t1 + b1), fp16 in/out -------------------
__global__ void k_agg(const __half* __restrict__ hin,
                      __half* __restrict__ hout,
                      const float* __restrict__ bias) {
    int node = (blockIdx.x * blockDim.x + threadIdx.x) >> 5;
    if (node >= N_NODES) return;
    int lane = threadIdx.x & 31;

    const uint2* hp = (const uint2*)hin;
    const float4 b = ((const float4*)bias)[lane];
    float4 r = gather_row16(hp, node, lane, b);
    ((uint2*)hout)[(size_t)node * 32 + lane] = f4toh4(r);
}

// ---------------- FUSED B: h2 = relu(A t2 + b2); pool atomics ---------------
#define HS 132
__global__ void __launch_bounds__(256) k_fused_ap(const __half* __restrict__ T2,
                                                  const float* __restrict__ bias,
                                                  const void* batchp) {
    __shared__ float sH[64 * HS];
    __shared__ int sg[64];

    const int tid = threadIdx.x;
    const int wid = tid >> 5, lane = tid & 31;
    const int rowBase = blockIdx.x * 64;
    const int n_here = min(64, N_NODES - rowBase);

    if (tid < 64 && rowBase + tid < N_NODES) {
        sg[tid] = load_idx(batchp, rowBase + tid);
        g_deg[rowBase + tid] = 0;            // prep next replay
    }

    const uint2* hp = (const uint2*)T2;
    const float4 bvec = ((const float4*)bias)[lane];
    #pragma unroll
    for (int i = 0; i < 8; i++) {
        int r = wid * 8 + i;
        int node = rowBase + r;
        if (node < N_NODES) {
            float4 v = gather_row16(hp, node, lane, bvec);
            *(float4*)&sH[r * HS + lane * 4] = v;
        }
    }
    __syncthreads();

    // ---- pool: run-length accumulate, rare atomics (batch sorted) ----
    if (tid < 128) {
        float acc = 0.f;
        int cur = sg[0];
        int runstart = 0;
        for (int n = 0; n < n_here; n++) {
            int g = sg[n];
            if (g != cur) {
                atomicAdd(&g_pool[cur * D + tid], acc);
                if (tid == 0) atomicAdd(&g_cnt[cur], n - runstart);
                acc = 0.f; cur = g; runstart = n;
            }
            acc += sH[n * HS + tid];
        }
        atomicAdd(&g_pool[cur * D + tid], acc);
        if (tid == 0) atomicAdd(&g_cnt[cur], n_here - runstart);
    }
}

// ---------------- final FC: out = relu( (pool/cnt) @ Wfc + bfc ) ------------
__global__ void k_fc(const float* __restrict__ Wfc,
                     const float* __restrict__ bfc,
                     float* __restrict__ out) {
    __shared__ float srow[D];
    int g = blockIdx.x;
    int t = threadIdx.x;
    float cnt = fmaxf((float)g_cnt[g], 1.0f);
    srow[t] = g_pool[g * D + t] / cnt;
    __syncthreads();
    float acc = bfc[t];
    #pragma unroll 4
    for (int k = 0; k < D; k++)
        acc = fmaf(srow[k], Wfc[k * D + t], acc);
    out[g * D + t] = fmaxf(acc, 0.f);
}

// ---------------- launch ----------------------------------------------------
extern "C" void kernel_launch(void* const* d_in, const int* in_sizes, int n_in,
                              void* d_out, int out_size) {
    const float* x    = (const float*)d_in[0];
    const void*  edge = d_in[1];
    const void*  batch= d_in[2];
    const float* W1   = (const float*)d_in[3];
    const float* b1   = (const float*)d_in[4];
    const float* W2   = (const float*)d_in[5];
    const float* b2   = (const float*)d_in[6];
    const float* Wfc  = (const float*)d_in[7];
    const float* bfc  = (const float*)d_in[8];
    float* out = (float*)d_out;

    void *px16, *pt1, *pt2, *ph1, *pw;
    cudaGetSymbolAddress(&px16, g_x16);
    cudaGetSymbolAddress(&pt1, g_t1);
    cudaGetSymbolAddress(&pt2, g_t2);
    cudaGetSymbolAddress(&ph1, g_h1);
    cudaGetSymbolAddress(&pw, g_W16);
    uint2* x16 = (uint2*)px16;
    __half* t1 = (__half*)pt1;
    __half* t2 = (__half*)pt2;
    __half* h1 = (__half*)ph1;
    uint32_t* wp = (uint32_t*)pw;

    cudaFuncSetAttribute(k_gemm,
                         cudaFuncAttributeMaxDynamicSharedMemorySize, GEMM_SMEM);

    const int EB = (N_EDGES + 255) / 256;
    const int GEMM_GRID = (N_NODES + 64 * SUBT - 1) / (64 * SUBT);  // 391
    const int TILE_GRID = (N_NODES + 63) / 64;                      // 1563
    const int AGG_BLOCKS = (N_NODES * 32 + 255) / 256;              // 12500

    // ---- preprocessing (also converts X -> fp16) ----
    k_deg<<<EB, 256>>>(edge, x, W1, W2);
    k_scan<<<NB, SCAN_T>>>();
    k_scatter<<<EB, 256>>>(edge);

    // ---- layer 1: t1 = X@W1 (fp16); h1 = relu(A t1 + b1) (fp16) ----
    k_gemm<<<GEMM_GRID, 256, GEMM_SMEM>>>(x16, wp, t1);
    k_agg<<<AGG_BLOCKS, 256>>>(t1, h1, b1);

    // ---- layer 2: t2 = h1@W2 (fp16); fused agg2 + pool ----
    k_gemm<<<GEMM_GRID, 256, GEMM_SMEM>>>((const uint2*)h1, wp + D * 64, t2);
    k_fused_ap<<<TILE_GRID, 256>>>(t2, b2, batch);

    // ---- fc ----
    k_fc<<<N_GRAPHS, D>>>(Wfc, bfc, out);
}

// round 12
// speedup vs baseline: 1.3948x; 1.0016x over previous
#include <cuda_runtime.h>
#include <cuda_bf16.h>
#include <cuda_fp16.h>
#include <cstdint>

#define N_NODES 100000
#define N_EDGES 1600000
#define N_GRAPHS 64
#define D 128

#define SCAN_T 1024
#define NB ((N_NODES + SCAN_T - 1) / SCAN_T)   // 98

// ---------------- scratch (device globals; no allocation allowed) ----------
__device__ uint2  g_x16[(size_t)N_NODES * 32]; // X in fp16 (packed 4/uint2)
__device__ __half g_t1[(size_t)N_NODES * D];  // X@W1, fp16
__device__ __half g_h1[(size_t)N_NODES * D];  // relu(A t1 + b1), fp16
__device__ __half g_t2[(size_t)N_NODES * D];  // h1@W2, fp16
__device__ int   g_deg[N_NODES];              // zeroed by k_fused_ap for next call
__device__ float g_dinv[N_NODES];
__device__ int   g_off[N_NODES + 1];
__device__ int   g_cur[N_NODES];
__device__ uint2 g_csr[N_EDGES];              // .x = src, .y = weight bits
__device__ int   g_bsum[NB];                  // re-armed to -1 by k_deg
__device__ float g_pool[N_GRAPHS * D];        // zeroed by k_gemm
__device__ int   g_cnt[N_GRAPHS];
__device__ int   g_is64;
__device__ uint32_t g_W16[2][D * 64];         // W^T fp16, packed pairs [n][k/2]

// ---------------- helpers ---------------------------------------------------
__device__ __forceinline__ int load_idx(const void* p, long long i) {
    if (g_is64) return (int)((const long long*)p)[i];
    return ((const int*)p)[i];
}

__device__ __forceinline__ int detect64(const void* ep) {
    const int* p = (const int*)ep;
    int is64 = 1;
    #pragma unroll
    for (int j = 0; j < 8; j++)
        if (p[2 * j + 1] != 0) is64 = 0;
    return is64;
}

// fp16 x fp16 -> fp32 MMA (exact products, fp32 accumulate)
__device__ __forceinline__ void mma16f(float* c, const uint32_t* a,
                                       const uint32_t* b) {
    asm volatile(
        "mma.sync.aligned.m16n8k16.row.col.f32.f16.f16.f32 "
        "{%0,%1,%2,%3}, {%4,%5,%6,%7}, {%8,%9}, {%0,%1,%2,%3};"
        : "+f"(c[0]), "+f"(c[1]), "+f"(c[2]), "+f"(c[3])
        : "r"(a[0]), "r"(a[1]), "r"(a[2]), "r"(a[3]), "r"(b[0]), "r"(b[1]));
}

__device__ __forceinline__ void ldsm_x4(uint32_t& r0, uint32_t& r1,
                                        uint32_t& r2, uint32_t& r3,
                                        uint32_t addr) {
    asm volatile(
        "ldmatrix.sync.aligned.m8n8.x4.shared.b16 {%0,%1,%2,%3}, [%4];"
        : "=r"(r0), "=r"(r1), "=r"(r2), "=r"(r3) : "r"(addr));
}

__device__ __forceinline__ uint32_t sptr(const void* p) {
    return (uint32_t)__cvta_generic_to_shared(p);
}

// async 16B global->shared copy; srcsize=0 zero-fills (boundary rows)
__device__ __forceinline__ void cp_async16(uint32_t dst, const void* src,
                                           uint32_t srcsize) {
    asm volatile("cp.async.ca.shared.global [%0], [%1], 16, %2;"
                 :: "r"(dst), "l"(src), "r"(srcsize) : "memory");
}
__device__ __forceinline__ void cp_commit() {
    asm volatile("cp.async.commit_group;" ::: "memory");
}
template <int N>
__device__ __forceinline__ void cp_wait() {
    asm volatile("cp.async.wait_group %0;" :: "n"(N) : "memory");
}

__device__ __forceinline__ float4 h4tof4(uint2 v) {
    float2 a = __half22float2(*reinterpret_cast<__half2*>(&v.x));
    float2 b = __half22float2(*reinterpret_cast<__half2*>(&v.y));
    return make_float4(a.x, a.y, b.x, b.y);
}

__device__ __forceinline__ uint2 f4toh4(float4 v) {
    __half2 a = __float22half2_rn(make_float2(v.x, v.y));
    __half2 b = __float22half2_rn(make_float2(v.z, v.w));
    uint2 o;
    o.x = *reinterpret_cast<uint32_t*>(&a);
    o.y = *reinterpret_cast<uint32_t*>(&b);
    return o;
}

// gather one node row from fp16 features:
// relu( dinv^2*h[node] + sum_e w*h[src] + bias )
__device__ __forceinline__ float4 gather_row16(const uint2* __restrict__ hp,
                                               int node, int lane,
                                               const float4 b) {
    float dii = g_dinv[node];
    float sw = dii * dii;
    float4 s = h4tof4(hp[(size_t)node * 32 + lane]);
    float4 acc[4];
    acc[0] = make_float4(s.x * sw, s.y * sw, s.z * sw, s.w * sw);
    acc[1] = make_float4(0.f, 0.f, 0.f, 0.f);
    acc[2] = acc[1];
    acc[3] = acc[1];

    int e = g_off[node];
    const int end = g_off[node + 1];
    for (; e + 3 < end; e += 4) {
        uint2 p[4];
        #pragma unroll
        for (int j = 0; j < 4; j++) p[j] = g_csr[e + j];
        uint2 raw[4];
        #pragma unroll
        for (int j = 0; j < 4; j++) raw[j] = hp[(size_t)p[j].x * 32 + lane];
        #pragma unroll
        for (int j = 0; j < 4; j++) {
            float w = __uint_as_float(p[j].y);
            float4 v = h4tof4(raw[j]);
            acc[j].x = fmaf(v.x, w, acc[j].x);
            acc[j].y = fmaf(v.y, w, acc[j].y);
            acc[j].z = fmaf(v.z, w, acc[j].z);
            acc[j].w = fmaf(v.w, w, acc[j].w);
        }
    }
    for (; e < end; e++) {
        uint2 p = g_csr[e];
        float w = __uint_as_float(p.y);
        float4 v = h4tof4(hp[(size_t)p.x * 32 + lane]);
        acc[0].x = fmaf(v.x, w, acc[0].x);
        acc[0].y = fmaf(v.y, w, acc[0].y);
        acc[0].z = fmaf(v.z, w, acc[0].z);
        acc[0].w = fmaf(v.w, w, acc[0].w);
    }
    float4 r;
    r.x = fmaxf(acc[0].x + acc[1].x + acc[2].x + acc[3].x + b.x, 0.f);
    r.y = fmaxf(acc[0].y + acc[1].y + acc[2].y + acc[3].y + b.y, 0.f);
    r.z = fmaxf(acc[0].z + acc[1].z + acc[2].z + acc[3].z + b.z, 0.f);
    r.w = fmaxf(acc[0].w + acc[1].w + acc[2].w + acc[3].w + b.w, 0.f);
    return r;
}

// ---------------- deg count + init (W fp16, X fp16, dtype, sentinels) -------
__global__ void k_deg(const void* ep, const float* X,
                      const float* W1, const float* W2) {
    int i = blockIdx.x * blockDim.x + threadIdx.x;
    if (i == 0) {
        g_is64 = detect64(ep);
        g_off[N_NODES] = N_EDGES;
    }
    if (i < NB) g_bsum[i] = -1;    // arm scan publication sentinel
    if (i < 2 * D * 64) {          // one packed fp16 pair of W^T per thread
        int m = i >> 13;           // 0 -> W1, 1 -> W2
        int j = i & 8191;
        int n = j >> 6, kp = j & 63;
        const float* W = m ? W2 : W1;
        float a = W[(2 * kp) * D + n];       // W^T[n][2kp]
        float b = W[(2 * kp + 1) * D + n];
        __half2 h = __float22half2_rn(make_float2(a, b));
        g_W16[m][n * 64 + kp] = *reinterpret_cast<uint32_t*>(&h);
    }
    // convert X to fp16 (2 uint2 per thread; 1.6M threads cover 3.2M exactly)
    #pragma unroll
    for (int j = 0; j < 2; j++) {
        int idx = i + j * (N_NODES * 16);   // 1,600,000 stride
        if (idx < N_NODES * 32)
            g_x16[idx] = f4toh4(((const float4*)X)[idx]);
    }
    if (i < N_EDGES) {
        int is64 = detect64(ep);
        int d = is64 ? (int)((const long long*)ep)[(long long)N_EDGES + i]
                     : ((const int*)ep)[N_EDGES + i];
        atomicAdd(&g_deg[d], 1);
    }
}

// ---------------- single-pass scan (98 blocks = 1 wave; spin publication) ---
__global__ void k_scan() {
    __shared__ int s[SCAN_T];
    __shared__ int s_boff;
    const int b = blockIdx.x;
    const int t = threadIdx.x;
    const int i = b * SCAN_T + t;
    int v = (i < N_NODES) ? g_deg[i] : 0;
    if (i < N_NODES) g_dinv[i] = rsqrtf((float)v + 1.0f);  // +1 self loop
    s[t] = v;
    if (t == 0) s_boff = 0;
    __syncthreads();
    #pragma unroll
    for (int off = 1; off < SCAN_T; off <<= 1) {
        int u = (t >= off) ? s[t - off] : 0;
        __syncthreads();
        s[t] += u;
        __syncthreads();
    }
    if (t == SCAN_T - 1)
        ((volatile int*)g_bsum)[b] = s[SCAN_T - 1];
    if (t < b) {
        int val;
        do { val = ((volatile int*)g_bsum)[t]; } while (val < 0);
        atomicAdd(&s_boff, val);
    }
    __syncthreads();
    if (i < N_NODES) {
        int off = s[t] - v + s_boff;
        g_off[i] = off;
        g_cur[i] = off;
    }
}

// ---------------- CSR scatter (counting sort by dst, packed 8B entries) -----
__global__ void k_scatter(const void* ep) {
    int e = blockIdx.x * blockDim.x + threadIdx.x;
    if (e >= N_EDGES) return;
    int s = load_idx(ep, e);
    int d = load_idx(ep, (long long)N_EDGES + e);
    int pos = atomicAdd(&g_cur[d], 1);
    float w = g_dinv[s] * g_dinv[d];
    g_csr[pos] = make_uint2((uint32_t)s, __float_as_uint(w));
}

// ---------------- GEMM: Y16 = X16 @ W (fp16 MMA, cp.async pipeline) ---------
// CTA: 256 thr; W staged once; double-buffered A via cp.async (no reg cost).
#define KS 136
#define SUBT 4
#define ABUF (64 * KS)                         // halfs per A buffer
#define GEMM_SMEM ((2 * ABUF + 128 * KS) * 2)  // 69632 B -> 3 CTAs/SM

__global__ void __launch_bounds__(256, 3) k_gemm(const uint2* __restrict__ X16,
                                                 const uint32_t* __restrict__ Wp,
                                                 __half* __restrict__ Y16) {
    extern __shared__ __half sm[];
    __half* sA = sm;                 // 2 x [64][136]
    __half* sW = sA + 2 * ABUF;      // [128][136]

    const int tid = threadIdx.x;
    const int rowBase0 = blockIdx.x * (64 * SUBT);
    const uint32_t sA0 = sptr(sA);
    const char* Xb = (const char*)X16;   // byte view; row = 256 B

    // zero pool/cnt for this call's fused_ap (idempotent)
    int gtid = blockIdx.x * 256 + tid;
    if (gtid < N_GRAPHS * D) g_pool[gtid] = 0.0f;
    if (gtid < N_GRAPHS) g_cnt[gtid] = 0;

    // staging: 4 x 16B per thread; i = tid + j*256 -> row i>>4, chunk i&15
    int sr[4], sc[4];
    #pragma unroll
    for (int j = 0; j < 4; j++) {
        int i = tid + j * 256;
        sr[j] = i >> 4;
        sc[j] = i & 15;
    }

    // ---- prologue: stage sub-tile 0 into buffer 0 (async) ----
    #pragma unroll
    for (int j = 0; j < 4; j++) {
        int row = rowBase0 + sr[j];
        cp_async16(sA0 + sr[j] * (KS * 2) + sc[j] * 16,
                   Xb + (size_t)row * 256 + sc[j] * 16,
                   row < N_NODES ? 16u : 0u);
    }
    cp_commit();

    // ---- stage W once (fp16) ----
    const uint4* Wp4 = (const uint4*)Wp;
    uint32_t* sW32 = (uint32_t*)sW;
    #pragma unroll
    for (int i = tid; i < 128 * 16; i += 256) {
        int n = i >> 4, kq = i & 15;
        *(uint4*)&sW32[n * (KS / 2) + kq * 4] = Wp4[i];
    }

    const int wid = tid >> 5, lane = tid & 31;
    const int g = lane >> 2, tg = lane & 3;
    const int mbase = (wid >> 2) * 32;
    const int nbase = (wid & 3) * 32;

    // ldmatrix lane addressing
    const int jj = lane >> 3, rr = lane & 7;
    uint32_t aBase[2];            // relative to sA buffer 0
    #pragma unroll
    for (int mf = 0; mf < 2; mf++) {
        int row = mbase + mf * 16 + ((jj & 1) * 8) + rr;
        int col = (jj >> 1) * 8;
        aBase[mf] = sptr(&sA[row * KS + col]);
    }
    uint32_t bBase[2];
    #pragma unroll
    for (int p = 0; p < 2; p++) {
        int row = nbase + p * 16 + ((jj >> 1) * 8) + rr;
        int col = (jj & 1) * 8;
        bBase[p] = sptr(&sW[row * KS + col]);
    }

    for (int st = 0; st < SUBT; st++) {
        const int rowBase = rowBase0 + st * 64;
        const uint32_t abytes = (uint32_t)((st & 1) * ABUF * 2);

        // ---- issue async stage for st+1 into the other buffer ----
        if (st + 1 < SUBT) {
            uint32_t dstb = sA0 + ((st + 1) & 1) * (ABUF * 2);
            #pragma unroll
            for (int j = 0; j < 4; j++) {
                int row = rowBase + 64 + sr[j];
                cp_async16(dstb + sr[j] * (KS * 2) + sc[j] * 16,
                           Xb + (size_t)row * 256 + sc[j] * 16,
                           row < N_NODES ? 16u : 0u);
            }
            cp_commit();
            cp_wait<1>();   // tile st complete (st+1 may stay in flight)
        } else {
            cp_wait<0>();
        }
        __syncthreads();

        // ---- MMA on buffer st&1 ----
        float acc[2][4][4];
        #pragma unroll
        for (int mf = 0; mf < 2; mf++)
            #pragma unroll
            for (int nf = 0; nf < 4; nf++)
                #pragma unroll
                for (int j = 0; j < 4; j++) acc[mf][nf][j] = 0.f;

        #pragma unroll
        for (int kc = 0; kc < 8; kc++) {
            const uint32_t koff = kc * 32;
            uint32_t a[2][4];
            #pragma unroll
            for (int mf = 0; mf < 2; mf++)
                ldsm_x4(a[mf][0], a[mf][1], a[mf][2], a[mf][3],
                        aBase[mf] + abytes + koff);
            uint32_t b[4][2];
            #pragma unroll
            for (int p = 0; p < 2; p++)
                ldsm_x4(b[2 * p][0], b[2 * p][1], b[2 * p + 1][0],
                        b[2 * p + 1][1], bBase[p] + koff);
            #pragma unroll
            for (int mf = 0; mf < 2; mf++)
                #pragma unroll
                for (int nf = 0; nf < 4; nf++)
                    mma16f(acc[mf][nf], a[mf], b[nf]);
        }

        // ---- epilogue: fp16 out ----
        #pragma unroll
        for (int mf = 0; mf < 2; mf++) {
            int row = rowBase + mbase + mf * 16 + g;
            #pragma unroll
            for (int nf = 0; nf < 4; nf++) {
                int col = nbase + nf * 8 + 2 * tg;
                if (row < N_NODES) {
                    __half2 h = __float22half2_rn(
                        make_float2(acc[mf][nf][0], acc[mf][nf][1]));
                    *(__half2*)&Y16[(size_t)row * D + col] = h;
                }
                if (row + 8 < N_NODES) {
                    __half2 h = __float22half2_rn(
                        make_float2(acc[mf][nf][2], acc[mf][nf][3]));
                    *(__half2*)&Y16[(size_t)(row + 8) * D + col] = h;
                }
            }
        }
        // WAR guard: next iter's cp.async writes the buffer read in iter st-1;
        // this sync orders all warps' ldsm reads of THIS iter before the
        // cp.async issued at the top of the next iter.
        __syncthreads();
    }
}

// ---------------- agg1: h1 = relu(A t1 + b1), fp16 in/out -------------------
__global__ void k_agg(const __half* __restrict__ hin,
                      __half* __restrict__ hout,
                      const float* __restrict__ bias) {
    int node = (blockIdx.x * blockDim.x + threadIdx.x) >> 5;
    if (node >= N_NODES) return;
    int lane = threadIdx.x & 31;

    const uint2* hp = (const uint2*)hin;
    const float4 b = ((const float4*)bias)[lane];
    float4 r = gather_row16(hp, node, lane, b);
    ((uint2*)hout)[(size_t)node * 32 + lane] = f4toh4(r);
}

// ---------------- FUSED B: h2 = relu(A t2 + b2); pool atomics ---------------
#define HS 132
__global__ void __launch_bounds__(256) k_fused_ap(const __half* __restrict__ T2,
                                                  const float* __restrict__ bias,
                                                  const void* batchp) {
    __shared__ float sH[64 * HS];
    __shared__ int sg[64];

    const int tid = threadIdx.x;
    const int wid = tid >> 5, lane = tid & 31;
    const int rowBase = blockIdx.x * 64;
    const int n_here = min(64, N_NODES - rowBase);

    if (tid < 64 && rowBase + tid < N_NODES) {
        sg[tid] = load_idx(batchp, rowBase + tid);
        g_deg[rowBase + tid] = 0;            // prep next replay
    }

    const uint2* hp = (const uint2*)T2;
    const float4 bvec = ((const float4*)bias)[lane];
    #pragma unroll
    for (int i = 0; i < 8; i++) {
        int r = wid * 8 + i;
        int node = rowBase + r;
        if (node < N_NODES) {
            float4 v = gather_row16(hp, node, lane, bvec);
            *(float4*)&sH[r * HS + lane * 4] = v;
        }
    }
    __syncthreads();

    // ---- pool: run-length accumulate, rare atomics (batch sorted) ----
    if (tid < 128) {
        float acc = 0.f;
        int cur = sg[0];
        int runstart = 0;
        for (int n = 0; n < n_here; n++) {
            int g = sg[n];
            if (g != cur) {
                atomicAdd(&g_pool[cur * D + tid], acc);
                if (tid == 0) atomicAdd(&g_cnt[cur], n - runstart);
                acc = 0.f; cur = g; runstart = n;
            }
            acc += sH[n * HS + tid];
        }
        atomicAdd(&g_pool[cur * D + tid], acc);
        if (tid == 0) atomicAdd(&g_cnt[cur], n_here - runstart);
    }
}

// ---------------- final FC: out = relu( (pool/cnt) @ Wfc + bfc ) ------------
__global__ void k_fc(const float* __restrict__ Wfc,
                     const float* __restrict__ bfc,
                     float* __restrict__ out) {
    __shared__ float srow[D];
    int g = blockIdx.x;
    int t = threadIdx.x;
    float cnt = fmaxf((float)g_cnt[g], 1.0f);
    srow[t] = g_pool[g * D + t] / cnt;
    __syncthreads();
    float acc = bfc[t];
    #pragma unroll 4
    for (int k = 0; k < D; k++)
        acc = fmaf(srow[k], Wfc[k * D + t], acc);
    out[g * D + t] = fmaxf(acc, 0.f);
}

// ---------------- launch ----------------------------------------------------
extern "C" void kernel_launch(void* const* d_in, const int* in_sizes, int n_in,
                              void* d_out, int out_size) {
    const float* x    = (const float*)d_in[0];
    const void*  edge = d_in[1];
    const void*  batch= d_in[2];
    const float* W1   = (const float*)d_in[3];
    const float* b1   = (const float*)d_in[4];
    const float* W2   = (const float*)d_in[5];
    const float* b2   = (const float*)d_in[6];
    const float* Wfc  = (const float*)d_in[7];
    const float* bfc  = (const float*)d_in[8];
    float* out = (float*)d_out;

    void *px16, *pt1, *pt2, *ph1, *pw;
    cudaGetSymbolAddress(&px16, g_x16);
    cudaGetSymbolAddress(&pt1, g_t1);
    cudaGetSymbolAddress(&pt2, g_t2);
    cudaGetSymbolAddress(&ph1, g_h1);
    cudaGetSymbolAddress(&pw, g_W16);
    uint2* x16 = (uint2*)px16;
    __half* t1 = (__half*)pt1;
    __half* t2 = (__half*)pt2;
    __half* h1 = (__half*)ph1;
    uint32_t* wp = (uint32_t*)pw;

    cudaFuncSetAttribute(k_gemm,
                         cudaFuncAttributeMaxDynamicSharedMemorySize, GEMM_SMEM);

    const int EB = (N_EDGES + 255) / 256;
    const int GEMM_GRID = (N_NODES + 64 * SUBT - 1) / (64 * SUBT);  // 391
    const int TILE_GRID = (N_NODES + 63) / 64;                      // 1563
    const int AGG_BLOCKS = (N_NODES * 32 + 255) / 256;              // 12500

    // ---- preprocessing (also converts X -> fp16) ----
    k_deg<<<EB, 256>>>(edge, x, W1, W2);
    k_scan<<<NB, SCAN_T>>>();
    k_scatter<<<EB, 256>>>(edge);

    // ---- layer 1: t1 = X@W1 (fp16); h1 = relu(A t1 + b1) (fp16) ----
    k_gemm<<<GEMM_GRID, 256, GEMM_SMEM>>>(x16, wp, t1);
    k_agg<<<AGG_BLOCKS, 256>>>(t1, h1, b1);

    // ---- layer 2: t2 = h1@W2 (fp16); fused agg2 + pool ----
    k_gemm<<<GEMM_GRID, 256, GEMM_SMEM>>>((const uint2*)h1, wp + D * 64, t2);
    k_fused_ap<<<TILE_GRID, 256>>>(t2, b2, batch);

    // ---- fc ----
    k_fc<<<N_GRAPHS, D>>>(Wfc, bfc, out);
}

// round 13
// speedup vs baseline: 1.4024x; 1.0054x over previous
#include <cuda_runtime.h>
#include <cuda_bf16.h>
#include <cuda_fp16.h>
#include <cstdint>

#define N_NODES 100000
#define N_EDGES 1600000
#define N_GRAPHS 64
#define D 128

#define SCAN_T 1024
#define NB ((N_NODES + SCAN_T - 1) / SCAN_T)   // 98

// ---------------- scratch (device globals; no allocation allowed) ----------
__device__ uint2  g_x16[(size_t)N_NODES * 32]; // X in fp16 (packed 4/uint2)
__device__ __half g_t1[(size_t)N_NODES * D];  // X@W1, fp16
__device__ __half g_h1[(size_t)N_NODES * D];  // relu(A t1 + b1), fp16
__device__ __half g_t2[(size_t)N_NODES * D];  // h1@W2, fp16
__device__ int   g_deg[N_NODES];              // zeroed by k_fused_ap for next call
__device__ float g_dinv[N_NODES];
__device__ int   g_off[N_NODES + 1];
__device__ int   g_cur[N_NODES];
__device__ uint2 g_csr[N_EDGES];              // .x = src, .y = weight bits
__device__ int   g_bsum[NB];                  // re-armed to -1 by k_deg
__device__ float g_pool[N_GRAPHS * D];        // zeroed by k_gemm
__device__ int   g_cnt[N_GRAPHS];
__device__ int   g_is64;
__device__ uint32_t g_W16[2][D * 64];         // W^T fp16, packed pairs [n][k/2]

// ---------------- helpers ---------------------------------------------------
__device__ __forceinline__ int load_idx(const void* p, long long i) {
    if (g_is64) return (int)((const long long*)p)[i];
    return ((const int*)p)[i];
}

__device__ __forceinline__ int detect64(const void* ep) {
    const int* p = (const int*)ep;
    int is64 = 1;
    #pragma unroll
    for (int j = 0; j < 8; j++)
        if (p[2 * j + 1] != 0) is64 = 0;
    return is64;
}

// fp16 x fp16 -> fp32 MMA (exact products, fp32 accumulate)
__device__ __forceinline__ void mma16f(float* c, const uint32_t* a,
                                       const uint32_t* b) {
    asm volatile(
        "mma.sync.aligned.m16n8k16.row.col.f32.f16.f16.f32 "
        "{%0,%1,%2,%3}, {%4,%5,%6,%7}, {%8,%9}, {%0,%1,%2,%3};"
        : "+f"(c[0]), "+f"(c[1]), "+f"(c[2]), "+f"(c[3])
        : "r"(a[0]), "r"(a[1]), "r"(a[2]), "r"(a[3]), "r"(b[0]), "r"(b[1]));
}

__device__ __forceinline__ void ldsm_x4(uint32_t& r0, uint32_t& r1,
                                        uint32_t& r2, uint32_t& r3,
                                        uint32_t addr) {
    asm volatile(
        "ldmatrix.sync.aligned.m8n8.x4.shared.b16 {%0,%1,%2,%3}, [%4];"
        : "=r"(r0), "=r"(r1), "=r"(r2), "=r"(r3) : "r"(addr));
}

__device__ __forceinline__ uint32_t sptr(const void* p) {
    return (uint32_t)__cvta_generic_to_shared(p);
}

// async 16B global->shared copy; srcsize=0 zero-fills (boundary rows)
__device__ __forceinline__ void cp_async16(uint32_t dst, const void* src,
                                           uint32_t srcsize) {
    asm volatile("cp.async.ca.shared.global [%0], [%1], 16, %2;"
                 :: "r"(dst), "l"(src), "r"(srcsize) : "memory");
}
__device__ __forceinline__ void cp_commit() {
    asm volatile("cp.async.commit_group;" ::: "memory");
}
template <int N>
__device__ __forceinline__ void cp_wait() {
    asm volatile("cp.async.wait_group %0;" :: "n"(N) : "memory");
}

__device__ __forceinline__ float4 h4tof4(uint2 v) {
    float2 a = __half22float2(*reinterpret_cast<__half2*>(&v.x));
    float2 b = __half22float2(*reinterpret_cast<__half2*>(&v.y));
    return make_float4(a.x, a.y, b.x, b.y);
}

__device__ __forceinline__ uint2 f4toh4(float4 v) {
    __half2 a = __float22half2_rn(make_float2(v.x, v.y));
    __half2 b = __float22half2_rn(make_float2(v.z, v.w));
    uint2 o;
    o.x = *reinterpret_cast<uint32_t*>(&a);
    o.y = *reinterpret_cast<uint32_t*>(&b);
    return o;
}

// gather one node row from fp16 features:
// relu( dinv^2*h[node] + sum_e w*h[src] + bias )
__device__ __forceinline__ float4 gather_row16(const uint2* __restrict__ hp,
                                               int node, int lane,
                                               const float4 b) {
    float dii = g_dinv[node];
    float sw = dii * dii;
    float4 s = h4tof4(hp[(size_t)node * 32 + lane]);
    float4 acc[4];
    acc[0] = make_float4(s.x * sw, s.y * sw, s.z * sw, s.w * sw);
    acc[1] = make_float4(0.f, 0.f, 0.f, 0.f);
    acc[2] = acc[1];
    acc[3] = acc[1];

    int e = g_off[node];
    const int end = g_off[node + 1];
    for (; e + 3 < end; e += 4) {
        uint2 p[4];
        #pragma unroll
        for (int j = 0; j < 4; j++) p[j] = g_csr[e + j];
        uint2 raw[4];
        #pragma unroll
        for (int j = 0; j < 4; j++) raw[j] = hp[(size_t)p[j].x * 32 + lane];
        #pragma unroll
        for (int j = 0; j < 4; j++) {
            float w = __uint_as_float(p[j].y);
            float4 v = h4tof4(raw[j]);
            acc[j].x = fmaf(v.x, w, acc[j].x);
            acc[j].y = fmaf(v.y, w, acc[j].y);
            acc[j].z = fmaf(v.z, w, acc[j].z);
            acc[j].w = fmaf(v.w, w, acc[j].w);
        }
    }
    for (; e < end; e++) {
        uint2 p = g_csr[e];
        float w = __uint_as_float(p.y);
        float4 v = h4tof4(hp[(size_t)p.x * 32 + lane]);
        acc[0].x = fmaf(v.x, w, acc[0].x);
        acc[0].y = fmaf(v.y, w, acc[0].y);
        acc[0].z = fmaf(v.z, w, acc[0].z);
        acc[0].w = fmaf(v.w, w, acc[0].w);
    }
    float4 r;
    r.x = fmaxf(acc[0].x + acc[1].x + acc[2].x + acc[3].x + b.x, 0.f);
    r.y = fmaxf(acc[0].y + acc[1].y + acc[2].y + acc[3].y + b.y, 0.f);
    r.z = fmaxf(acc[0].z + acc[1].z + acc[2].z + acc[3].z + b.z, 0.f);
    r.w = fmaxf(acc[0].w + acc[1].w + acc[2].w + acc[3].w + b.w, 0.f);
    return r;
}

// ---------------- branch B: convert W + X to fp16 ----------------------------
__global__ void k_conv(const float* X, const float* W1, const float* W2) {
    int i = blockIdx.x * blockDim.x + threadIdx.x;
    if (i < 2 * D * 64) {          // one packed fp16 pair of W^T per thread
        int m = i >> 13;           // 0 -> W1, 1 -> W2
        int j = i & 8191;
        int n = j >> 6, kp = j & 63;
        const float* W = m ? W2 : W1;
        float a = W[(2 * kp) * D + n];       // W^T[n][2kp]
        float b = W[(2 * kp + 1) * D + n];
        __half2 h = __float22half2_rn(make_float2(a, b));
        g_W16[m][n * 64 + kp] = *reinterpret_cast<uint32_t*>(&h);
    }
    // convert X to fp16 (2 uint2 per thread; 1.6M threads cover 3.2M exactly)
    #pragma unroll
    for (int j = 0; j < 2; j++) {
        int idx = i + j * (N_NODES * 16);
        if (idx < N_NODES * 32)
            g_x16[idx] = f4toh4(((const float4*)X)[idx]);
    }
}

// ---------------- branch A: deg count + dtype + sentinels --------------------
__global__ void k_deg(const void* ep) {
    int i = blockIdx.x * blockDim.x + threadIdx.x;
    if (i == 0) {
        g_is64 = detect64(ep);
        g_off[N_NODES] = N_EDGES;
    }
    if (i < NB) g_bsum[i] = -1;    // arm scan publication sentinel
    if (i < N_EDGES) {
        int is64 = detect64(ep);
        int d = is64 ? (int)((const long long*)ep)[(long long)N_EDGES + i]
                     : ((const int*)ep)[N_EDGES + i];
        atomicAdd(&g_deg[d], 1);
    }
}

// ---------------- single-pass scan (98 blocks = 1 wave; spin publication) ---
__global__ void k_scan() {
    __shared__ int s[SCAN_T];
    __shared__ int s_boff;
    const int b = blockIdx.x;
    const int t = threadIdx.x;
    const int i = b * SCAN_T + t;
    int v = (i < N_NODES) ? g_deg[i] : 0;
    if (i < N_NODES) g_dinv[i] = rsqrtf((float)v + 1.0f);  // +1 self loop
    s[t] = v;
    if (t == 0) s_boff = 0;
    __syncthreads();
    #pragma unroll
    for (int off = 1; off < SCAN_T; off <<= 1) {
        int u = (t >= off) ? s[t - off] : 0;
        __syncthreads();
        s[t] += u;
        __syncthreads();
    }
    if (t == SCAN_T - 1)
        ((volatile int*)g_bsum)[b] = s[SCAN_T - 1];
    if (t < b) {
        int val;
        do { val = ((volatile int*)g_bsum)[t]; } while (val < 0);
        atomicAdd(&s_boff, val);
    }
    __syncthreads();
    if (i < N_NODES) {
        int off = s[t] - v + s_boff;
        g_off[i] = off;
        g_cur[i] = off;
    }
}

// ---------------- CSR scatter (counting sort by dst, packed 8B entries) -----
__global__ void k_scatter(const void* ep) {
    int e = blockIdx.x * blockDim.x + threadIdx.x;
    if (e >= N_EDGES) return;
    int s = load_idx(ep, e);
    int d = load_idx(ep, (long long)N_EDGES + e);
    int pos = atomicAdd(&g_cur[d], 1);
    float w = g_dinv[s] * g_dinv[d];
    g_csr[pos] = make_uint2((uint32_t)s, __float_as_uint(w));
}

// ---------------- GEMM: Y16 = X16 @ W (fp16 MMA, cp.async pipeline) ---------
#define KS 136
#define SUBT 4
#define ABUF (64 * KS)                         // halfs per A buffer
#define GEMM_SMEM ((2 * ABUF + 128 * KS) * 2)  // 69632 B -> 3 CTAs/SM

__global__ void __launch_bounds__(256, 3) k_gemm(const uint2* __restrict__ X16,
                                                 const uint32_t* __restrict__ Wp,
                                                 __half* __restrict__ Y16) {
    extern __shared__ __half sm[];
    __half* sA = sm;                 // 2 x [64][136]
    __half* sW = sA + 2 * ABUF;      // [128][136]

    const int tid = threadIdx.x;
    const int rowBase0 = blockIdx.x * (64 * SUBT);
    const uint32_t sA0 = sptr(sA);
    const char* Xb = (const char*)X16;   // byte view; row = 256 B

    // zero pool/cnt for this call's fused_ap (idempotent)
    int gtid = blockIdx.x * 256 + tid;
    if (gtid < N_GRAPHS * D) g_pool[gtid] = 0.0f;
    if (gtid < N_GRAPHS) g_cnt[gtid] = 0;

    // staging: 4 x 16B per thread; i = tid + j*256 -> row i>>4, chunk i&15
    int sr[4], sc[4];
    #pragma unroll
    for (int j = 0; j < 4; j++) {
        int i = tid + j * 256;
        sr[j] = i >> 4;
        sc[j] = i & 15;
    }

    // ---- prologue: stage sub-tile 0 into buffer 0 (async) ----
    #pragma unroll
    for (int j = 0; j < 4; j++) {
        int row = rowBase0 + sr[j];
        cp_async16(sA0 + sr[j] * (KS * 2) + sc[j] * 16,
                   Xb + (size_t)row * 256 + sc[j] * 16,
                   row < N_NODES ? 16u : 0u);
    }
    cp_commit();

    // ---- stage W once (fp16) ----
    const uint4* Wp4 = (const uint4*)Wp;
    uint32_t* sW32 = (uint32_t*)sW;
    #pragma unroll
    for (int i = tid; i < 128 * 16; i += 256) {
        int n = i >> 4, kq = i & 15;
        *(uint4*)&sW32[n * (KS / 2) + kq * 4] = Wp4[i];
    }

    const int wid = tid >> 5, lane = tid & 31;
    const int g = lane >> 2, tg = lane & 3;
    const int mbase = (wid >> 2) * 32;
    const int nbase = (wid & 3) * 32;

    // ldmatrix lane addressing
    const int jj = lane >> 3, rr = lane & 7;
    uint32_t aBase[2];            // relative to sA buffer 0
    #pragma unroll
    for (int mf = 0; mf < 2; mf++) {
        int row = mbase + mf * 16 + ((jj & 1) * 8) + rr;
        int col = (jj >> 1) * 8;
        aBase[mf] = sptr(&sA[row * KS + col]);
    }
    uint32_t bBase[2];
    #pragma unroll
    for (int p = 0; p < 2; p++) {
        int row = nbase + p * 16 + ((jj >> 1) * 8) + rr;
        int col = (jj & 1) * 8;
        bBase[p] = sptr(&sW[row * KS + col]);
    }

    for (int st = 0; st < SUBT; st++) {
        const int rowBase = rowBase0 + st * 64;
        const uint32_t abytes = (uint32_t)((st & 1) * ABUF * 2);

        // ---- issue async stage for st+1 into the other buffer ----
        if (st + 1 < SUBT) {
            uint32_t dstb = sA0 + ((st + 1) & 1) * (ABUF * 2);
            #pragma unroll
            for (int j = 0; j < 4; j++) {
                int row = rowBase + 64 + sr[j];
                cp_async16(dstb + sr[j] * (KS * 2) + sc[j] * 16,
                           Xb + (size_t)row * 256 + sc[j] * 16,
                           row < N_NODES ? 16u : 0u);
            }
            cp_commit();
            cp_wait<1>();   // tile st complete (st+1 may stay in flight)
        } else {
            cp_wait<0>();
        }
        __syncthreads();

        // ---- MMA on buffer st&1 ----
        float acc[2][4][4];
        #pragma unroll
        for (int mf = 0; mf < 2; mf++)
            #pragma unroll
            for (int nf = 0; nf < 4; nf++)
                #pragma unroll
                for (int j = 0; j < 4; j++) acc[mf][nf][j] = 0.f;

        #pragma unroll
        for (int kc = 0; kc < 8; kc++) {
            const uint32_t koff = kc * 32;
            uint32_t a[2][4];
            #pragma unroll
            for (int mf = 0; mf < 2; mf++)
                ldsm_x4(a[mf][0], a[mf][1], a[mf][2], a[mf][3],
                        aBase[mf] + abytes + koff);
            uint32_t b[4][2];
            #pragma unroll
            for (int p = 0; p < 2; p++)
                ldsm_x4(b[2 * p][0], b[2 * p][1], b[2 * p + 1][0],
                        b[2 * p + 1][1], bBase[p] + koff);
            #pragma unroll
            for (int mf = 0; mf < 2; mf++)
                #pragma unroll
                for (int nf = 0; nf < 4; nf++)
                    mma16f(acc[mf][nf], a[mf], b[nf]);
        }

        // ---- epilogue: fp16 out ----
        #pragma unroll
        for (int mf = 0; mf < 2; mf++) {
            int row = rowBase + mbase + mf * 16 + g;
            #pragma unroll
            for (int nf = 0; nf < 4; nf++) {
                int col = nbase + nf * 8 + 2 * tg;
                if (row < N_NODES) {
                    __half2 h = __float22half2_rn(
                        make_float2(acc[mf][nf][0], acc[mf][nf][1]));
                    *(__half2*)&Y16[(size_t)row * D + col] = h;
                }
                if (row + 8 < N_NODES) {
                    __half2 h = __float22half2_rn(
                        make_float2(acc[mf][nf][2], acc[mf][nf][3]));
                    *(__half2*)&Y16[(size_t)(row + 8) * D + col] = h;
                }
            }
        }
        __syncthreads();   // WAR: reads done before next iter's cp.async
    }
}

// ---------------- agg1: h1 = relu(A t1 + b1), fp16 in/out -------------------
__global__ void k_agg(const __half* __restrict__ hin,
                      __half* __restrict__ hout,
                      const float* __restrict__ bias) {
    int node = (blockIdx.x * blockDim.x + threadIdx.x) >> 5;
    if (node >= N_NODES) return;
    int lane = threadIdx.x & 31;

    const uint2* hp = (const uint2*)hin;
    const float4 b = ((const float4*)bias)[lane];
    float4 r = gather_row16(hp, node, lane, b);
    ((uint2*)hout)[(size_t)node * 32 + lane] = f4toh4(r);
}

// ---------------- FUSED B: h2 = relu(A t2 + b2); pool atomics ---------------
#define HS 132
__global__ void __launch_bounds__(256) k_fused_ap(const __half* __restrict__ T2,
                                                  const float* __restrict__ bias,
                                                  const void* batchp) {
    __shared__ float sH[64 * HS];
    __shared__ int sg[64];

    const int tid = threadIdx.x;
    const int wid = tid >> 5, lane = tid & 31;
    const int rowBase = blockIdx.x * 64;
    const int n_here = min(64, N_NODES - rowBase);

    if (tid < 64 && rowBase + tid < N_NODES) {
        sg[tid] = load_idx(batchp, rowBase + tid);
        g_deg[rowBase + tid] = 0;            // prep next replay
    }

    const uint2* hp = (const uint2*)T2;
    const float4 bvec = ((const float4*)bias)[lane];
    #pragma unroll
    for (int i = 0; i < 8; i++) {
        int r = wid * 8 + i;
        int node = rowBase + r;
        if (node < N_NODES) {
            float4 v = gather_row16(hp, node, lane, bvec);
            *(float4*)&sH[r * HS + lane * 4] = v;
        }
    }
    __syncthreads();

    // ---- pool: run-length accumulate, rare atomics (batch sorted) ----
    if (tid < 128) {
        float acc = 0.f;
        int cur = sg[0];
        int runstart = 0;
        for (int n = 0; n < n_here; n++) {
            int g = sg[n];
            if (g != cur) {
                atomicAdd(&g_pool[cur * D + tid], acc);
                if (tid == 0) atomicAdd(&g_cnt[cur], n - runstart);
                acc = 0.f; cur = g; runstart = n;
            }
            acc += sH[n * HS + tid];
        }
        atomicAdd(&g_pool[cur * D + tid], acc);
        if (tid == 0) atomicAdd(&g_cnt[cur], n_here - runstart);
    }
}

// ---------------- final FC: out = relu( (pool/cnt) @ Wfc + bfc ) ------------
__global__ void k_fc(const float* __restrict__ Wfc,
                     const float* __restrict__ bfc,
                     float* __restrict__ out) {
    __shared__ float srow[D];
    int g = blockIdx.x;
    int t = threadIdx.x;
    float cnt = fmaxf((float)g_cnt[g], 1.0f);
    srow[t] = g_pool[g * D + t] / cnt;
    __syncthreads();
    float acc = bfc[t];
    #pragma unroll 4
    for (int k = 0; k < D; k++)
        acc = fmaf(srow[k], Wfc[k * D + t], acc);
    out[g * D + t] = fmaxf(acc, 0.f);
}

// ---------------- launch ----------------------------------------------------
extern "C" void kernel_launch(void* const* d_in, const int* in_sizes, int n_in,
                              void* d_out, int out_size) {
    const float* x    = (const float*)d_in[0];
    const void*  edge = d_in[1];
    const void*  batch= d_in[2];
    const float* W1   = (const float*)d_in[3];
    const float* b1   = (const float*)d_in[4];
    const float* W2   = (const float*)d_in[5];
    const float* b2   = (const float*)d_in[6];
    const float* Wfc  = (const float*)d_in[7];
    const float* bfc  = (const float*)d_in[8];
    float* out = (float*)d_out;

    void *px16, *pt1, *pt2, *ph1, *pw;
    cudaGetSymbolAddress(&px16, g_x16);
    cudaGetSymbolAddress(&pt1, g_t1);
    cudaGetSymbolAddress(&pt2, g_t2);
    cudaGetSymbolAddress(&ph1, g_h1);
    cudaGetSymbolAddress(&pw, g_W16);
    uint2* x16 = (uint2*)px16;
    __half* t1 = (__half*)pt1;
    __half* t2 = (__half*)pt2;
    __half* h1 = (__half*)ph1;
    uint32_t* wp = (uint32_t*)pw;

    cudaFuncSetAttribute(k_gemm,
                         cudaFuncAttributeMaxDynamicSharedMemorySize, GEMM_SMEM);

    const int EB = (N_EDGES + 255) / 256;
    const int GEMM_GRID = (N_NODES + 64 * SUBT - 1) / (64 * SUBT);  // 391
    const int TILE_GRID = (N_NODES + 63) / 64;                      // 1563
    const int AGG_BLOCKS = (N_NODES * 32 + 255) / 256;              // 12500

    // fork/join side stream (created per call; kernel_launch runs only a
    // few times host-side — replays reuse the captured graph)
    cudaStream_t s1 = nullptr;
    cudaEvent_t evFork = nullptr, evJoin = nullptr;
    bool forked =
        cudaStreamCreateWithFlags(&s1, cudaStreamNonBlocking) == cudaSuccess &&
        cudaEventCreateWithFlags(&evFork, cudaEventDisableTiming) == cudaSuccess &&
        cudaEventCreateWithFlags(&evJoin, cudaEventDisableTiming) == cudaSuccess;

    if (forked) {
        // ---- fork: branch B (convert + gemm1) on s1 ----
        cudaEventRecord(evFork, 0);
        cudaStreamWaitEvent(s1, evFork, 0);
        k_conv<<<EB, 256, 0, s1>>>(x, W1, W2);
        k_gemm<<<GEMM_GRID, 256, GEMM_SMEM, s1>>>(x16, wp, t1);
        cudaEventRecord(evJoin, s1);

        // ---- branch A (graph topology) on the main stream ----
        k_deg<<<EB, 256>>>(edge);
        k_scan<<<NB, SCAN_T>>>();
        k_scatter<<<EB, 256>>>(edge);

        // ---- join ----
        cudaStreamWaitEvent(0, evJoin, 0);
    } else {
        // sequential fallback
        k_conv<<<EB, 256>>>(x, W1, W2);
        k_deg<<<EB, 256>>>(edge);
        k_scan<<<NB, SCAN_T>>>();
        k_scatter<<<EB, 256>>>(edge);
        k_gemm<<<GEMM_GRID, 256, GEMM_SMEM>>>(x16, wp, t1);
    }

    // ---- layer 1 aggregation, layer 2, pool, fc (joined path) ----
    k_agg<<<AGG_BLOCKS, 256>>>(t1, h1, b1);
    k_gemm<<<GEMM_GRID, 256, GEMM_SMEM>>>((const uint2*)h1, wp + D * 64, t2);
    k_fused_ap<<<TILE_GRID, 256>>>(t2, b2, batch);
    k_fc<<<N_GRAPHS, D>>>(Wfc, bfc, out);
}